// round 3
// baseline (speedup 1.0000x reference)
#include <cuda_runtime.h>

#define NRES 512
#define DCH  128
#define NPOS (NRES*NRES)

// Scratch (device globals — no runtime allocation allowed)
__device__ float g_xln  [(size_t)NPOS * DCH];
__device__ float g_left [(size_t)NPOS * DCH];
__device__ float g_right[(size_t)NPOS * DCH];
__device__ float g_gate [(size_t)NPOS * DCH];
__device__ float g_pre  [(size_t)NPOS * DCH];

__device__ __forceinline__ float fsig(float x) { return 1.0f / (1.0f + __expf(-x)); }

__device__ __forceinline__ void cp16(void* s, const void* g) {
    unsigned sa = (unsigned)__cvta_generic_to_shared(s);
    asm volatile("cp.async.cg.shared.global [%0], [%1], 16;" :: "r"(sa), "l"(g));
}

// ---------------------------------------------------------------------------
// K1: LayerNorm over D=128. One warp per row (float4/lane), 8 rows per block.
// ---------------------------------------------------------------------------
__global__ void ln_kernel(const float* __restrict__ pair,
                          const float* __restrict__ lng,
                          const float* __restrict__ lnb)
{
    const int lane = threadIdx.x & 31;
    const int row  = blockIdx.x * 8 + (threadIdx.x >> 5);
    const float4 v = reinterpret_cast<const float4*>(pair)[(size_t)row * 32 + lane];
    float s = v.x + v.y + v.z + v.w;
    float q = v.x*v.x + v.y*v.y + v.z*v.z + v.w*v.w;
#pragma unroll
    for (int o = 16; o > 0; o >>= 1) {
        s += __shfl_xor_sync(0xffffffffu, s, o);
        q += __shfl_xor_sync(0xffffffffu, q, o);
    }
    const float mean = s * (1.0f / 128.0f);
    const float var  = q * (1.0f / 128.0f) - mean * mean;
    const float rs   = rsqrtf(var + 1e-5f);
    const float4 g4 = reinterpret_cast<const float4*>(lng)[lane];
    const float4 b4 = reinterpret_cast<const float4*>(lnb)[lane];
    float4 o4;
    o4.x = (v.x - mean) * rs * g4.x + b4.x;
    o4.y = (v.y - mean) * rs * g4.y + b4.y;
    o4.z = (v.z - mean) * rs * g4.z + b4.z;
    o4.w = (v.w - mean) * rs * g4.w + b4.w;
    reinterpret_cast<float4*>(g_xln)[(size_t)row * 32 + lane] = o4;
}

// ---------------------------------------------------------------------------
// K2: fused dual projection: dst = (x@Wp + bp) * sigmoid(x@Wg + bg) * mask
// Block tile: 64 rows x 128 cols, K=128 in 4 chunks of 32. 256 threads.
// DST: 0 -> g_left, 1 -> g_right
// ---------------------------------------------------------------------------
template<int DST>
__global__ __launch_bounds__(256) void proj_pg_kernel(
    const float* __restrict__ wp, const float* __restrict__ bp,
    const float* __restrict__ wg, const float* __restrict__ bg,
    const float* __restrict__ mask)
{
    __shared__ float  sA [64][32];
    __shared__ float4 sWp[32][32];
    __shared__ float4 sWg[32][32];
    float* __restrict__ dst = (DST == 0) ? g_left : g_right;

    const int t    = threadIdx.x;
    const int row0 = blockIdx.x * 64;
    const int tx   = t & 31;     // output col group (4 cols)
    const int ty   = t >> 5;     // row group (8 rows)

    float4 aP[8], aG[8];
#pragma unroll
    for (int r = 0; r < 8; r++) { aP[r] = make_float4(0.f,0.f,0.f,0.f); aG[r] = aP[r]; }

    for (int kc = 0; kc < 4; kc++) {
#pragma unroll
        for (int q = 0; q < 8; q++) {
            int idx = t + q * 256;
            sA[idx >> 5][idx & 31] =
                g_xln[(size_t)(row0 + (idx >> 5)) * DCH + kc * 32 + (idx & 31)];
        }
#pragma unroll
        for (int q = 0; q < 4; q++) {
            int idx = t + q * 256;
            int r = idx >> 5, c = idx & 31;
            sWp[r][c] = reinterpret_cast<const float4*>(wp)[(size_t)(kc*32 + r)*32 + c];
            sWg[r][c] = reinterpret_cast<const float4*>(wg)[(size_t)(kc*32 + r)*32 + c];
        }
        __syncthreads();
#pragma unroll
        for (int k = 0; k < 32; k++) {
            const float4 wpv = sWp[k][tx];
            const float4 wgv = sWg[k][tx];
#pragma unroll
            for (int r = 0; r < 8; r++) {
                const float a = sA[ty*8 + r][k];
                aP[r].x += a*wpv.x; aP[r].y += a*wpv.y; aP[r].z += a*wpv.z; aP[r].w += a*wpv.w;
                aG[r].x += a*wgv.x; aG[r].y += a*wgv.y; aG[r].z += a*wgv.z; aG[r].w += a*wgv.w;
            }
        }
        __syncthreads();
    }
    const float4 bpv = reinterpret_cast<const float4*>(bp)[tx];
    const float4 bgv = reinterpret_cast<const float4*>(bg)[tx];
#pragma unroll
    for (int r = 0; r < 8; r++) {
        const int row = row0 + ty*8 + r;
        const float m = mask[row];
        float4 o;
        o.x = (aP[r].x + bpv.x) * fsig(aG[r].x + bgv.x) * m;
        o.y = (aP[r].y + bpv.y) * fsig(aG[r].y + bgv.y) * m;
        o.z = (aP[r].z + bpv.z) * fsig(aG[r].z + bgv.z) * m;
        o.w = (aP[r].w + bpv.w) * fsig(aG[r].w + bgv.w) * m;
        reinterpret_cast<float4*>(dst)[(size_t)row * 32 + tx] = o;
    }
}

// ---------------------------------------------------------------------------
// K3: single projection.
// MODE 1: g_gate = sigmoid(g_xln @ w + b)
// MODE 0: out    = g_pre @ w + b      (final output projection)
// ---------------------------------------------------------------------------
template<int MODE>
__global__ __launch_bounds__(256) void proj_single_kernel(
    const float* __restrict__ w, const float* __restrict__ b,
    float* __restrict__ out)
{
    __shared__ float  sA[64][32];
    __shared__ float4 sW[32][32];
    const float* __restrict__ src = (MODE == 1) ? g_xln : g_pre;
    float* __restrict__ dst = (MODE == 1) ? g_gate : out;

    const int t    = threadIdx.x;
    const int row0 = blockIdx.x * 64;
    const int tx   = t & 31;
    const int ty   = t >> 5;

    float4 acc[8];
#pragma unroll
    for (int r = 0; r < 8; r++) acc[r] = make_float4(0.f,0.f,0.f,0.f);

    for (int kc = 0; kc < 4; kc++) {
#pragma unroll
        for (int q = 0; q < 8; q++) {
            int idx = t + q * 256;
            sA[idx >> 5][idx & 31] =
                src[(size_t)(row0 + (idx >> 5)) * DCH + kc * 32 + (idx & 31)];
        }
#pragma unroll
        for (int q = 0; q < 4; q++) {
            int idx = t + q * 256;
            sW[idx >> 5][idx & 31] =
                reinterpret_cast<const float4*>(w)[(size_t)(kc*32 + (idx>>5))*32 + (idx&31)];
        }
        __syncthreads();
#pragma unroll
        for (int k = 0; k < 32; k++) {
            const float4 wv = sW[k][tx];
#pragma unroll
            for (int r = 0; r < 8; r++) {
                const float a = sA[ty*8 + r][k];
                acc[r].x += a*wv.x; acc[r].y += a*wv.y; acc[r].z += a*wv.z; acc[r].w += a*wv.w;
            }
        }
        __syncthreads();
    }
    const float4 bv = reinterpret_cast<const float4*>(b)[tx];
#pragma unroll
    for (int r = 0; r < 8; r++) {
        const int row = row0 + ty*8 + r;
        float4 o;
        o.x = acc[r].x + bv.x; o.y = acc[r].y + bv.y;
        o.z = acc[r].z + bv.z; o.w = acc[r].w + bv.w;
        if (MODE == 1) { o.x = fsig(o.x); o.y = fsig(o.y); o.z = fsig(o.z); o.w = fsig(o.w); }
        reinterpret_cast<float4*>(dst)[(size_t)row * 32 + tx] = o;
    }
}

// ---------------------------------------------------------------------------
// K4: einsum  pre[i,k,d] = (sum_j left[i,j,d] * right[j,k,d]) * gate[i,k,d]
// Channel-vectorized: lane owns float4 of d (32 lanes = 128 channels).
// Block: 256 thr = 8 warps; tile 16i x 16k; warp = 4i x 8k; loop j with
// cp.async double buffering. 8x8 block supertile swizzle for L2 reuse.
// ---------------------------------------------------------------------------
__global__ __launch_bounds__(256, 1) void einsum_kernel()
{
    __shared__ float4 sL[2][16][32];
    __shared__ float4 sR[2][16][32];

    const int t    = threadIdx.x;
    const int lane = t & 31;
    const int wid  = t >> 5;
    const int wi   = wid & 3;   // i sub-group (4 rows)
    const int wk   = wid >> 2;  // k sub-group (8 cols)

    const int bId = blockIdx.x;
    const int grp = bId >> 6;                       // 16 supertiles (4x4)
    const int loc = bId & 63;                       // 8x8 within supertile
    const int bi  = ((grp >> 2) << 3) + (loc >> 3); // 0..31
    const int bk  = ((grp &  3) << 3) + (loc &  7); // 0..31
    const int i0  = bi * 16, k0 = bk * 16;

    const float4* __restrict__ L4 = reinterpret_cast<const float4*>(g_left);
    const float4* __restrict__ R4 = reinterpret_cast<const float4*>(g_right);

    const int d4  = t & 31;
    const int iiA = t >> 5;  // 0..7 -> rows iiA and iiA+8

    float4 acc[4][8];
#pragma unroll
    for (int a = 0; a < 4; a++)
#pragma unroll
        for (int c = 0; c < 8; c++) acc[a][c] = make_float4(0.f,0.f,0.f,0.f);

    auto load_stage = [&](int j, int buf) {
#pragma unroll
        for (int h = 0; h < 2; h++) {
            const int ii = iiA + h * 8;
            cp16(&sL[buf][ii][d4], &L4[((size_t)(i0 + ii) * NRES + j) * 32 + d4]);
            cp16(&sR[buf][ii][d4], &R4[((size_t)j * NRES + (k0 + ii)) * 32 + d4]);
        }
        asm volatile("cp.async.commit_group;");
    };

    load_stage(0, 0);

    for (int j = 0; j < NRES; j++) {
        asm volatile("cp.async.wait_group 0;");
        __syncthreads();                       // stage j visible to all
        if (j + 1 < NRES) load_stage(j + 1, (j + 1) & 1);  // overlap with compute
        const int buf = j & 1;
        float4 la[4];
#pragma unroll
        for (int a = 0; a < 4; a++) la[a] = sL[buf][wi*4 + a][lane];
#pragma unroll
        for (int c = 0; c < 8; c++) {
            const float4 rb = sR[buf][wk*8 + c][lane];
#pragma unroll
            for (int a = 0; a < 4; a++) {
                acc[a][c].x += la[a].x * rb.x;
                acc[a][c].y += la[a].y * rb.y;
                acc[a][c].z += la[a].z * rb.z;
                acc[a][c].w += la[a].w * rb.w;
            }
        }
    }

    const float4* __restrict__ G4 = reinterpret_cast<const float4*>(g_gate);
    float4* __restrict__ P4 = reinterpret_cast<float4*>(g_pre);
#pragma unroll
    for (int a = 0; a < 4; a++) {
        const int i = i0 + wi*4 + a;
#pragma unroll
        for (int c = 0; c < 8; c++) {
            const int k = k0 + wk*8 + c;
            const size_t pos = (size_t)i * NRES + k;
            const float4 gt = G4[pos * 32 + lane];
            float4 o = acc[a][c];
            o.x *= gt.x; o.y *= gt.y; o.z *= gt.z; o.w *= gt.w;
            P4[pos * 32 + lane] = o;
        }
    }
}

// ---------------------------------------------------------------------------
extern "C" void kernel_launch(void* const* d_in, const int* in_sizes, int n_in,
                              void* d_out, int out_size)
{
    const float* pair = (const float*)d_in[0];
    const float* mask = (const float*)d_in[1];
    const float* ln_g = (const float*)d_in[2];
    const float* ln_b = (const float*)d_in[3];
    const float* w_lp = (const float*)d_in[4];
    const float* b_lp = (const float*)d_in[5];
    const float* w_lg = (const float*)d_in[6];
    const float* b_lg = (const float*)d_in[7];
    const float* w_rp = (const float*)d_in[8];
    const float* b_rp = (const float*)d_in[9];
    const float* w_rg = (const float*)d_in[10];
    const float* b_rg = (const float*)d_in[11];
    const float* w_g  = (const float*)d_in[12];
    const float* b_g  = (const float*)d_in[13];
    const float* w_o  = (const float*)d_in[14];
    const float* b_o  = (const float*)d_in[15];
    float* out = (float*)d_out;

    ln_kernel<<<NPOS / 8, 256>>>(pair, ln_g, ln_b);
    proj_pg_kernel<0><<<NPOS / 64, 256>>>(w_lp, b_lp, w_lg, b_lg, mask);
    proj_pg_kernel<1><<<NPOS / 64, 256>>>(w_rp, b_rp, w_rg, b_rg, mask);
    proj_single_kernel<1><<<NPOS / 64, 256>>>(w_g, b_g, nullptr);
    einsum_kernel<<<1024, 256>>>();
    proj_single_kernel<0><<<NPOS / 64, 256>>>(w_o, b_o, out);
}

// round 5
// speedup vs baseline: 1.3168x; 1.3168x over previous
#include <cuda_runtime.h>

typedef unsigned long long u64;

#define NRES 512
#define DCH  128
#define NPOS (NRES*NRES)

// Scratch (device globals — no runtime allocation allowed)
__device__ float g_xln  [(size_t)NPOS * DCH];
__device__ float g_left [(size_t)NPOS * DCH];
__device__ float g_right[(size_t)NPOS * DCH];
__device__ float g_gate [(size_t)NPOS * DCH];
__device__ float g_pre  [(size_t)NPOS * DCH];

__device__ __forceinline__ float fsig(float x) { return 1.0f / (1.0f + __expf(-x)); }

__device__ __forceinline__ u64 fma2(u64 a, u64 b, u64 c) {
    u64 d;
    asm("fma.rn.f32x2 %0, %1, %2, %3;" : "=l"(d) : "l"(a), "l"(b), "l"(c));
    return d;
}
__device__ __forceinline__ u64 mul2(u64 a, u64 b) {
    u64 d;
    asm("mul.rn.f32x2 %0, %1, %2;" : "=l"(d) : "l"(a), "l"(b));
    return d;
}
__device__ __forceinline__ u64 dup2(float a) {
    u64 r;
    asm("mov.b64 %0, {%1, %1};" : "=l"(r) : "f"(a));
    return r;
}
__device__ __forceinline__ float2 unpk(u64 v) {
    float2 f;
    asm("mov.b64 {%0, %1}, %2;" : "=f"(f.x), "=f"(f.y) : "l"(v));
    return f;
}

__device__ __forceinline__ void cp16(void* s, const void* g) {
    unsigned sa = (unsigned)__cvta_generic_to_shared(s);
    asm volatile("cp.async.cg.shared.global [%0], [%1], 16;" :: "r"(sa), "l"(g));
}

// ---------------------------------------------------------------------------
// K1: LayerNorm over D=128. One warp per row (float4/lane), 8 rows per block.
// ---------------------------------------------------------------------------
__global__ void ln_kernel(const float* __restrict__ pair,
                          const float* __restrict__ lng,
                          const float* __restrict__ lnb)
{
    const int lane = threadIdx.x & 31;
    const int row  = blockIdx.x * 8 + (threadIdx.x >> 5);
    const float4 v = reinterpret_cast<const float4*>(pair)[(size_t)row * 32 + lane];
    float s = v.x + v.y + v.z + v.w;
    float q = v.x*v.x + v.y*v.y + v.z*v.z + v.w*v.w;
#pragma unroll
    for (int o = 16; o > 0; o >>= 1) {
        s += __shfl_xor_sync(0xffffffffu, s, o);
        q += __shfl_xor_sync(0xffffffffu, q, o);
    }
    const float mean = s * (1.0f / 128.0f);
    const float var  = q * (1.0f / 128.0f) - mean * mean;
    const float rs   = rsqrtf(var + 1e-5f);
    const float4 g4 = reinterpret_cast<const float4*>(lng)[lane];
    const float4 b4 = reinterpret_cast<const float4*>(lnb)[lane];
    float4 o4;
    o4.x = (v.x - mean) * rs * g4.x + b4.x;
    o4.y = (v.y - mean) * rs * g4.y + b4.y;
    o4.z = (v.z - mean) * rs * g4.z + b4.z;
    o4.w = (v.w - mean) * rs * g4.w + b4.w;
    reinterpret_cast<float4*>(g_xln)[(size_t)row * 32 + lane] = o4;
}

// ---------------------------------------------------------------------------
// K2: x -> left = (x@Wlp+blp)*sig(x@Wlg+blg)*mask,  gate = sig(x@Wg+bg)
// Block: 64 rows x 128 cols, K in 8 chunks of 16. 256 threads.
// Packed fp32x2 math with A duplicated in smem.
// ---------------------------------------------------------------------------
__global__ __launch_bounds__(256) void proj_left_gate(
    const float* __restrict__ wlp, const float* __restrict__ blp,
    const float* __restrict__ wlg, const float* __restrict__ blg,
    const float* __restrict__ wg,  const float* __restrict__ bg,
    const float* __restrict__ mask)
{
    __shared__ u64    sAd[64][16];
    __shared__ float4 sWp[16][32];
    __shared__ float4 sWq[16][32];
    __shared__ float4 sWr[16][32];

    const int t    = threadIdx.x;
    const int row0 = blockIdx.x * 64;
    const int tx   = t & 31;     // 4 output cols
    const int ty   = t >> 5;     // 8 rows

    u64 aP[8][2], aG[8][2], aH[8][2];
#pragma unroll
    for (int r = 0; r < 8; r++) {
        aP[r][0] = aP[r][1] = 0ull;
        aG[r][0] = aG[r][1] = 0ull;
        aH[r][0] = aH[r][1] = 0ull;
    }

    for (int kc = 0; kc < 8; kc++) {
#pragma unroll
        for (int q = 0; q < 4; q++) {
            int idx = t + q * 256;
            int row = idx >> 4, kk = idx & 15;
            float a = g_xln[(size_t)(row0 + row) * DCH + kc * 16 + kk];
            sAd[row][kk] = dup2(a);
        }
#pragma unroll
        for (int q = 0; q < 2; q++) {
            int idx = t + q * 256;
            int r = idx >> 5, c = idx & 31;
            sWp[r][c] = reinterpret_cast<const float4*>(wlp)[(size_t)(kc*16 + r)*32 + c];
            sWq[r][c] = reinterpret_cast<const float4*>(wlg)[(size_t)(kc*16 + r)*32 + c];
            sWr[r][c] = reinterpret_cast<const float4*>(wg )[(size_t)(kc*16 + r)*32 + c];
        }
        __syncthreads();
#pragma unroll
        for (int k = 0; k < 16; k += 2) {
            const ulonglong2 wp0 = *reinterpret_cast<const ulonglong2*>(&sWp[k  ][tx]);
            const ulonglong2 wp1 = *reinterpret_cast<const ulonglong2*>(&sWp[k+1][tx]);
            const ulonglong2 wq0 = *reinterpret_cast<const ulonglong2*>(&sWq[k  ][tx]);
            const ulonglong2 wq1 = *reinterpret_cast<const ulonglong2*>(&sWq[k+1][tx]);
            const ulonglong2 wr0 = *reinterpret_cast<const ulonglong2*>(&sWr[k  ][tx]);
            const ulonglong2 wr1 = *reinterpret_cast<const ulonglong2*>(&sWr[k+1][tx]);
#pragma unroll
            for (int r = 0; r < 8; r++) {
                const ulonglong2 ad = *reinterpret_cast<const ulonglong2*>(&sAd[ty*8 + r][k]);
                aP[r][0] = fma2(ad.x, wp0.x, aP[r][0]);
                aP[r][1] = fma2(ad.x, wp0.y, aP[r][1]);
                aP[r][0] = fma2(ad.y, wp1.x, aP[r][0]);
                aP[r][1] = fma2(ad.y, wp1.y, aP[r][1]);
                aG[r][0] = fma2(ad.x, wq0.x, aG[r][0]);
                aG[r][1] = fma2(ad.x, wq0.y, aG[r][1]);
                aG[r][0] = fma2(ad.y, wq1.x, aG[r][0]);
                aG[r][1] = fma2(ad.y, wq1.y, aG[r][1]);
                aH[r][0] = fma2(ad.x, wr0.x, aH[r][0]);
                aH[r][1] = fma2(ad.x, wr0.y, aH[r][1]);
                aH[r][0] = fma2(ad.y, wr1.x, aH[r][0]);
                aH[r][1] = fma2(ad.y, wr1.y, aH[r][1]);
            }
        }
        __syncthreads();
    }
    const float4 bpv = reinterpret_cast<const float4*>(blp)[tx];
    const float4 bqv = reinterpret_cast<const float4*>(blg)[tx];
    const float4 brv = reinterpret_cast<const float4*>(bg )[tx];
#pragma unroll
    for (int r = 0; r < 8; r++) {
        const int row = row0 + ty*8 + r;
        const float m = mask[row];
        float2 p0 = unpk(aP[r][0]), p1 = unpk(aP[r][1]);
        float2 g0 = unpk(aG[r][0]), g1 = unpk(aG[r][1]);
        float2 h0 = unpk(aH[r][0]), h1 = unpk(aH[r][1]);
        float4 oL, oG;
        oL.x = (p0.x + bpv.x) * fsig(g0.x + bqv.x) * m;
        oL.y = (p0.y + bpv.y) * fsig(g0.y + bqv.y) * m;
        oL.z = (p1.x + bpv.z) * fsig(g1.x + bqv.z) * m;
        oL.w = (p1.y + bpv.w) * fsig(g1.y + bqv.w) * m;
        oG.x = fsig(h0.x + brv.x);
        oG.y = fsig(h0.y + brv.y);
        oG.z = fsig(h1.x + brv.z);
        oG.w = fsig(h1.y + brv.w);
        reinterpret_cast<float4*>(g_left)[(size_t)row * 32 + tx] = oL;
        reinterpret_cast<float4*>(g_gate)[(size_t)row * 32 + tx] = oG;
    }
}

// ---------------------------------------------------------------------------
// K3: x -> right = (x@Wrp+brp)*sig(x@Wrg+brg)*mask
// ---------------------------------------------------------------------------
__global__ __launch_bounds__(256) void proj_right(
    const float* __restrict__ wrp, const float* __restrict__ brp,
    const float* __restrict__ wrg, const float* __restrict__ brg,
    const float* __restrict__ mask)
{
    __shared__ u64    sAd[64][16];
    __shared__ float4 sWp[16][32];
    __shared__ float4 sWq[16][32];

    const int t    = threadIdx.x;
    const int row0 = blockIdx.x * 64;
    const int tx   = t & 31;
    const int ty   = t >> 5;

    u64 aP[8][2], aG[8][2];
#pragma unroll
    for (int r = 0; r < 8; r++) {
        aP[r][0] = aP[r][1] = 0ull;
        aG[r][0] = aG[r][1] = 0ull;
    }

    for (int kc = 0; kc < 8; kc++) {
#pragma unroll
        for (int q = 0; q < 4; q++) {
            int idx = t + q * 256;
            int row = idx >> 4, kk = idx & 15;
            float a = g_xln[(size_t)(row0 + row) * DCH + kc * 16 + kk];
            sAd[row][kk] = dup2(a);
        }
#pragma unroll
        for (int q = 0; q < 2; q++) {
            int idx = t + q * 256;
            int r = idx >> 5, c = idx & 31;
            sWp[r][c] = reinterpret_cast<const float4*>(wrp)[(size_t)(kc*16 + r)*32 + c];
            sWq[r][c] = reinterpret_cast<const float4*>(wrg)[(size_t)(kc*16 + r)*32 + c];
        }
        __syncthreads();
#pragma unroll
        for (int k = 0; k < 16; k += 2) {
            const ulonglong2 wp0 = *reinterpret_cast<const ulonglong2*>(&sWp[k  ][tx]);
            const ulonglong2 wp1 = *reinterpret_cast<const ulonglong2*>(&sWp[k+1][tx]);
            const ulonglong2 wq0 = *reinterpret_cast<const ulonglong2*>(&sWq[k  ][tx]);
            const ulonglong2 wq1 = *reinterpret_cast<const ulonglong2*>(&sWq[k+1][tx]);
#pragma unroll
            for (int r = 0; r < 8; r++) {
                const ulonglong2 ad = *reinterpret_cast<const ulonglong2*>(&sAd[ty*8 + r][k]);
                aP[r][0] = fma2(ad.x, wp0.x, aP[r][0]);
                aP[r][1] = fma2(ad.x, wp0.y, aP[r][1]);
                aP[r][0] = fma2(ad.y, wp1.x, aP[r][0]);
                aP[r][1] = fma2(ad.y, wp1.y, aP[r][1]);
                aG[r][0] = fma2(ad.x, wq0.x, aG[r][0]);
                aG[r][1] = fma2(ad.x, wq0.y, aG[r][1]);
                aG[r][0] = fma2(ad.y, wq1.x, aG[r][0]);
                aG[r][1] = fma2(ad.y, wq1.y, aG[r][1]);
            }
        }
        __syncthreads();
    }
    const float4 bpv = reinterpret_cast<const float4*>(brp)[tx];
    const float4 bqv = reinterpret_cast<const float4*>(brg)[tx];
#pragma unroll
    for (int r = 0; r < 8; r++) {
        const int row = row0 + ty*8 + r;
        const float m = mask[row];
        float2 p0 = unpk(aP[r][0]), p1 = unpk(aP[r][1]);
        float2 g0 = unpk(aG[r][0]), g1 = unpk(aG[r][1]);
        float4 o;
        o.x = (p0.x + bpv.x) * fsig(g0.x + bqv.x) * m;
        o.y = (p0.y + bpv.y) * fsig(g0.y + bqv.y) * m;
        o.z = (p1.x + bpv.z) * fsig(g1.x + bqv.z) * m;
        o.w = (p1.y + bpv.w) * fsig(g1.y + bqv.w) * m;
        reinterpret_cast<float4*>(g_right)[(size_t)row * 32 + tx] = o;
    }
}

// ---------------------------------------------------------------------------
// K4: out = g_pre @ w_o + b_o
// ---------------------------------------------------------------------------
__global__ __launch_bounds__(256) void proj_out(
    const float* __restrict__ w, const float* __restrict__ b,
    float* __restrict__ out)
{
    __shared__ u64    sAd[64][16];
    __shared__ float4 sW[16][32];

    const int t    = threadIdx.x;
    const int row0 = blockIdx.x * 64;
    const int tx   = t & 31;
    const int ty   = t >> 5;

    u64 acc[8][2];
#pragma unroll
    for (int r = 0; r < 8; r++) acc[r][0] = acc[r][1] = 0ull;

    for (int kc = 0; kc < 8; kc++) {
#pragma unroll
        for (int q = 0; q < 4; q++) {
            int idx = t + q * 256;
            int row = idx >> 4, kk = idx & 15;
            float a = g_pre[(size_t)(row0 + row) * DCH + kc * 16 + kk];
            sAd[row][kk] = dup2(a);
        }
#pragma unroll
        for (int q = 0; q < 2; q++) {
            int idx = t + q * 256;
            int r = idx >> 5, c = idx & 31;
            sW[r][c] = reinterpret_cast<const float4*>(w)[(size_t)(kc*16 + r)*32 + c];
        }
        __syncthreads();
#pragma unroll
        for (int k = 0; k < 16; k += 2) {
            const ulonglong2 w0 = *reinterpret_cast<const ulonglong2*>(&sW[k  ][tx]);
            const ulonglong2 w1 = *reinterpret_cast<const ulonglong2*>(&sW[k+1][tx]);
#pragma unroll
            for (int r = 0; r < 8; r++) {
                const ulonglong2 ad = *reinterpret_cast<const ulonglong2*>(&sAd[ty*8 + r][k]);
                acc[r][0] = fma2(ad.x, w0.x, acc[r][0]);
                acc[r][1] = fma2(ad.x, w0.y, acc[r][1]);
                acc[r][0] = fma2(ad.y, w1.x, acc[r][0]);
                acc[r][1] = fma2(ad.y, w1.y, acc[r][1]);
            }
        }
        __syncthreads();
    }
    const float4 bv = reinterpret_cast<const float4*>(b)[tx];
#pragma unroll
    for (int r = 0; r < 8; r++) {
        const int row = row0 + ty*8 + r;
        float2 p0 = unpk(acc[r][0]), p1 = unpk(acc[r][1]);
        float4 o;
        o.x = p0.x + bv.x; o.y = p0.y + bv.y;
        o.z = p1.x + bv.z; o.w = p1.y + bv.w;
        reinterpret_cast<float4*>(out)[(size_t)row * 32 + tx] = o;
    }
}

// ---------------------------------------------------------------------------
// K5: einsum  pre[i,k,d] = (sum_j left[i,j,d] * right[j,k,d]) * gate[i,k,d]
// Channel-vectorized packed-fp32x2. 3-stage cp.async ring (48KB static smem),
// 16i x 16k tile, warp = 4i x 8k, 8x8 block supertile swizzle.
// RACE FIX vs R4: a cp.async group is committed EVERY iteration (empty groups
// are legal and complete instantly), so at each wait exactly 2 groups are
// pending and wait_group 1 always retires stage j's group — including the
// final two iterations, which previously read smem before the copy landed.
// ---------------------------------------------------------------------------
__global__ __launch_bounds__(256, 1) void einsum_kernel()
{
    __shared__ float4 sL[3][16][32];   // 24 KB
    __shared__ float4 sR[3][16][32];   // 24 KB

    const int t    = threadIdx.x;
    const int lane = t & 31;
    const int wid  = t >> 5;
    const int wi   = wid & 3;   // i sub-group (4 rows)
    const int wk   = wid >> 2;  // k sub-group (8 cols)

    const int bId = blockIdx.x;
    const int grp = bId >> 6;                       // 16 supertiles (4x4)
    const int loc = bId & 63;                       // 8x8 within supertile
    const int bi  = ((grp >> 2) << 3) + (loc >> 3);
    const int bk  = ((grp &  3) << 3) + (loc &  7);
    const int i0  = bi * 16, k0 = bk * 16;

    const float4* __restrict__ L4 = reinterpret_cast<const float4*>(g_left);
    const float4* __restrict__ R4 = reinterpret_cast<const float4*>(g_right);

    const int d4  = t & 31;
    const int iiA = t >> 5;  // rows iiA and iiA+8

    u64 accx[4][8], accy[4][8];
#pragma unroll
    for (int a = 0; a < 4; a++)
#pragma unroll
        for (int c = 0; c < 8; c++) { accx[a][c] = 0ull; accy[a][c] = 0ull; }

    // Issues the copies for stage j into buffer buf (no commit).
    auto issue_stage = [&](int j, int buf) {
#pragma unroll
        for (int h = 0; h < 2; h++) {
            const int ii = iiA + h * 8;
            cp16(&sL[buf][ii][d4], &L4[((size_t)(i0 + ii) * NRES + j) * 32 + d4]);
            cp16(&sR[buf][ii][d4], &R4[((size_t)j * NRES + (k0 + ii)) * 32 + d4]);
        }
    };

    issue_stage(0, 0);
    asm volatile("cp.async.commit_group;");
    issue_stage(1, 1);
    asm volatile("cp.async.commit_group;");

    int buf = 0;
    for (int j = 0; j < NRES; j++) {
        // Exactly 2 groups pending here (stages j, j+1); retire stage j.
        asm volatile("cp.async.wait_group 1;");
        __syncthreads();                 // stage j visible; all warps done with j-1
        if (j + 2 < NRES) {
            int nb = buf + 2; if (nb >= 3) nb -= 3;
            issue_stage(j + 2, nb);
        }
        asm volatile("cp.async.commit_group;");   // possibly-empty group: keeps count uniform
        ulonglong2 la[4];
#pragma unroll
        for (int a = 0; a < 4; a++)
            la[a] = *reinterpret_cast<const ulonglong2*>(&sL[buf][wi*4 + a][lane]);
#pragma unroll
        for (int c = 0; c < 8; c++) {
            const ulonglong2 rb = *reinterpret_cast<const ulonglong2*>(&sR[buf][wk*8 + c][lane]);
#pragma unroll
            for (int a = 0; a < 4; a++) {
                accx[a][c] = fma2(la[a].x, rb.x, accx[a][c]);
                accy[a][c] = fma2(la[a].y, rb.y, accy[a][c]);
            }
        }
        if (++buf == 3) buf = 0;
    }

    const ulonglong2* __restrict__ G2 =
        reinterpret_cast<const ulonglong2*>(g_gate);
    ulonglong2* __restrict__ P2 = reinterpret_cast<ulonglong2*>(g_pre);
#pragma unroll
    for (int a = 0; a < 4; a++) {
        const int i = i0 + wi*4 + a;
#pragma unroll
        for (int c = 0; c < 8; c++) {
            const int k = k0 + wk*8 + c;
            const size_t pos = (size_t)i * NRES + k;
            const ulonglong2 gt = G2[pos * 32 + lane];
            ulonglong2 o;
            o.x = mul2(accx[a][c], gt.x);
            o.y = mul2(accy[a][c], gt.y);
            P2[pos * 32 + lane] = o;
        }
    }
}

// ---------------------------------------------------------------------------
extern "C" void kernel_launch(void* const* d_in, const int* in_sizes, int n_in,
                              void* d_out, int out_size)
{
    const float* pair = (const float*)d_in[0];
    const float* mask = (const float*)d_in[1];
    const float* ln_g = (const float*)d_in[2];
    const float* ln_b = (const float*)d_in[3];
    const float* w_lp = (const float*)d_in[4];
    const float* b_lp = (const float*)d_in[5];
    const float* w_lg = (const float*)d_in[6];
    const float* b_lg = (const float*)d_in[7];
    const float* w_rp = (const float*)d_in[8];
    const float* b_rp = (const float*)d_in[9];
    const float* w_rg = (const float*)d_in[10];
    const float* b_rg = (const float*)d_in[11];
    const float* w_g  = (const float*)d_in[12];
    const float* b_g  = (const float*)d_in[13];
    const float* w_o  = (const float*)d_in[14];
    const float* b_o  = (const float*)d_in[15];
    float* out = (float*)d_out;

    ln_kernel<<<NPOS / 8, 256>>>(pair, ln_g, ln_b);
    proj_left_gate<<<NPOS / 64, 256>>>(w_lp, b_lp, w_lg, b_lg, w_g, b_g, mask);
    proj_right<<<NPOS / 64, 256>>>(w_rp, b_rp, w_rg, b_rg, mask);
    einsum_kernel<<<1024, 256>>>();
    proj_out<<<NPOS / 64, 256>>>(w_o, b_o, out);
}

// round 6
// speedup vs baseline: 1.4854x; 1.1280x over previous
#include <cuda_runtime.h>

typedef unsigned long long u64;

#define NRES 512
#define DCH  128
#define NPOS (NRES*NRES)

// Scratch (device globals — no runtime allocation allowed)
__device__ float g_xln  [(size_t)NPOS * DCH];
__device__ float g_left [(size_t)NPOS * DCH];
__device__ float g_right[(size_t)NPOS * DCH];
__device__ float g_gate [(size_t)NPOS * DCH];
__device__ float g_pre  [(size_t)NPOS * DCH];

__device__ __forceinline__ float fsig(float x) { return 1.0f / (1.0f + __expf(-x)); }

__device__ __forceinline__ u64 fma2(u64 a, u64 b, u64 c) {
    u64 d;
    asm("fma.rn.f32x2 %0, %1, %2, %3;" : "=l"(d) : "l"(a), "l"(b), "l"(c));
    return d;
}
__device__ __forceinline__ u64 mul2(u64 a, u64 b) {
    u64 d;
    asm("mul.rn.f32x2 %0, %1, %2;" : "=l"(d) : "l"(a), "l"(b));
    return d;
}
__device__ __forceinline__ u64 dup2(float a) {
    u64 r;
    asm("mov.b64 %0, {%1, %1};" : "=l"(r) : "f"(a));
    return r;
}
__device__ __forceinline__ float2 unpk(u64 v) {
    float2 f;
    asm("mov.b64 {%0, %1}, %2;" : "=f"(f.x), "=f"(f.y) : "l"(v));
    return f;
}

__device__ __forceinline__ void cp16(void* s, const void* g) {
    unsigned sa = (unsigned)__cvta_generic_to_shared(s);
    asm volatile("cp.async.cg.shared.global [%0], [%1], 16;" :: "r"(sa), "l"(g));
}

// ---------------------------------------------------------------------------
// K1: LayerNorm over D=128. One warp per row (float4/lane), 8 rows per block.
// ---------------------------------------------------------------------------
__global__ void ln_kernel(const float* __restrict__ pair,
                          const float* __restrict__ lng,
                          const float* __restrict__ lnb)
{
    const int lane = threadIdx.x & 31;
    const int row  = blockIdx.x * 8 + (threadIdx.x >> 5);
    const float4 v = reinterpret_cast<const float4*>(pair)[(size_t)row * 32 + lane];
    float s = v.x + v.y + v.z + v.w;
    float q = v.x*v.x + v.y*v.y + v.z*v.z + v.w*v.w;
#pragma unroll
    for (int o = 16; o > 0; o >>= 1) {
        s += __shfl_xor_sync(0xffffffffu, s, o);
        q += __shfl_xor_sync(0xffffffffu, q, o);
    }
    const float mean = s * (1.0f / 128.0f);
    const float var  = q * (1.0f / 128.0f) - mean * mean;
    const float rs   = rsqrtf(var + 1e-5f);
    const float4 g4 = reinterpret_cast<const float4*>(lng)[lane];
    const float4 b4 = reinterpret_cast<const float4*>(lnb)[lane];
    float4 o4;
    o4.x = (v.x - mean) * rs * g4.x + b4.x;
    o4.y = (v.y - mean) * rs * g4.y + b4.y;
    o4.z = (v.z - mean) * rs * g4.z + b4.z;
    o4.w = (v.w - mean) * rs * g4.w + b4.w;
    reinterpret_cast<float4*>(g_xln)[(size_t)row * 32 + lane] = o4;
}

// ---------------------------------------------------------------------------
// K2: dual projection: dst = (x@Wp+bp)*sig(x@Wg+bg)*mask
// DST 0 -> g_left, 1 -> g_right. 64 rows x 128 cols per block, 256 threads,
// 2 CTAs/SM (launch_bounds) so LDS/barrier latency is hidden.
// ---------------------------------------------------------------------------
template<int DST>
__global__ __launch_bounds__(256, 2) void proj_dual(
    const float* __restrict__ wp, const float* __restrict__ bp,
    const float* __restrict__ wg, const float* __restrict__ bg,
    const float* __restrict__ mask)
{
    __shared__ u64    sAd[64][16];
    __shared__ float4 sWp[16][32];
    __shared__ float4 sWq[16][32];
    float* __restrict__ dst = (DST == 0) ? g_left : g_right;

    const int t    = threadIdx.x;
    const int row0 = blockIdx.x * 64;
    const int tx   = t & 31;
    const int ty   = t >> 5;

    u64 aP[8][2], aG[8][2];
#pragma unroll
    for (int r = 0; r < 8; r++) {
        aP[r][0] = aP[r][1] = 0ull;
        aG[r][0] = aG[r][1] = 0ull;
    }

    for (int kc = 0; kc < 8; kc++) {
#pragma unroll
        for (int q = 0; q < 4; q++) {
            int idx = t + q * 256;
            int row = idx >> 4, kk = idx & 15;
            float a = g_xln[(size_t)(row0 + row) * DCH + kc * 16 + kk];
            sAd[row][kk] = dup2(a);
        }
#pragma unroll
        for (int q = 0; q < 2; q++) {
            int idx = t + q * 256;
            int r = idx >> 5, c = idx & 31;
            sWp[r][c] = reinterpret_cast<const float4*>(wp)[(size_t)(kc*16 + r)*32 + c];
            sWq[r][c] = reinterpret_cast<const float4*>(wg)[(size_t)(kc*16 + r)*32 + c];
        }
        __syncthreads();
#pragma unroll
        for (int k = 0; k < 16; k += 2) {
            const ulonglong2 wp0 = *reinterpret_cast<const ulonglong2*>(&sWp[k  ][tx]);
            const ulonglong2 wp1 = *reinterpret_cast<const ulonglong2*>(&sWp[k+1][tx]);
            const ulonglong2 wq0 = *reinterpret_cast<const ulonglong2*>(&sWq[k  ][tx]);
            const ulonglong2 wq1 = *reinterpret_cast<const ulonglong2*>(&sWq[k+1][tx]);
#pragma unroll
            for (int r = 0; r < 8; r++) {
                const ulonglong2 ad = *reinterpret_cast<const ulonglong2*>(&sAd[ty*8 + r][k]);
                aP[r][0] = fma2(ad.x, wp0.x, aP[r][0]);
                aP[r][1] = fma2(ad.x, wp0.y, aP[r][1]);
                aP[r][0] = fma2(ad.y, wp1.x, aP[r][0]);
                aP[r][1] = fma2(ad.y, wp1.y, aP[r][1]);
                aG[r][0] = fma2(ad.x, wq0.x, aG[r][0]);
                aG[r][1] = fma2(ad.x, wq0.y, aG[r][1]);
                aG[r][0] = fma2(ad.y, wq1.x, aG[r][0]);
                aG[r][1] = fma2(ad.y, wq1.y, aG[r][1]);
            }
        }
        __syncthreads();
    }
    const float4 bpv = reinterpret_cast<const float4*>(bp)[tx];
    const float4 bqv = reinterpret_cast<const float4*>(bg)[tx];
#pragma unroll
    for (int r = 0; r < 8; r++) {
        const int row = row0 + ty*8 + r;
        const float m = mask[row];
        float2 p0 = unpk(aP[r][0]), p1 = unpk(aP[r][1]);
        float2 g0 = unpk(aG[r][0]), g1 = unpk(aG[r][1]);
        float4 o;
        o.x = (p0.x + bpv.x) * fsig(g0.x + bqv.x) * m;
        o.y = (p0.y + bpv.y) * fsig(g0.y + bqv.y) * m;
        o.z = (p1.x + bpv.z) * fsig(g1.x + bqv.z) * m;
        o.w = (p1.y + bpv.w) * fsig(g1.y + bqv.w) * m;
        reinterpret_cast<float4*>(dst)[(size_t)row * 32 + tx] = o;
    }
}

// ---------------------------------------------------------------------------
// K3: single projection.
// MODE 1: g_gate = sigmoid(g_xln @ w + b);  MODE 0: out = g_pre @ w + b
// ---------------------------------------------------------------------------
template<int MODE>
__global__ __launch_bounds__(256, 2) void proj_single(
    const float* __restrict__ w, const float* __restrict__ b,
    float* __restrict__ out)
{
    __shared__ u64    sAd[64][16];
    __shared__ float4 sW[16][32];
    const float* __restrict__ src = (MODE == 1) ? g_xln : g_pre;
    float* __restrict__ dst = (MODE == 1) ? g_gate : out;

    const int t    = threadIdx.x;
    const int row0 = blockIdx.x * 64;
    const int tx   = t & 31;
    const int ty   = t >> 5;

    u64 acc[8][2];
#pragma unroll
    for (int r = 0; r < 8; r++) acc[r][0] = acc[r][1] = 0ull;

    for (int kc = 0; kc < 8; kc++) {
#pragma unroll
        for (int q = 0; q < 4; q++) {
            int idx = t + q * 256;
            int row = idx >> 4, kk = idx & 15;
            float a = src[(size_t)(row0 + row) * DCH + kc * 16 + kk];
            sAd[row][kk] = dup2(a);
        }
#pragma unroll
        for (int q = 0; q < 2; q++) {
            int idx = t + q * 256;
            sW[idx >> 5][idx & 31] =
                reinterpret_cast<const float4*>(w)[(size_t)(kc*16 + (idx>>5))*32 + (idx&31)];
        }
        __syncthreads();
#pragma unroll
        for (int k = 0; k < 16; k += 2) {
            const ulonglong2 w0 = *reinterpret_cast<const ulonglong2*>(&sW[k  ][tx]);
            const ulonglong2 w1 = *reinterpret_cast<const ulonglong2*>(&sW[k+1][tx]);
#pragma unroll
            for (int r = 0; r < 8; r++) {
                const ulonglong2 ad = *reinterpret_cast<const ulonglong2*>(&sAd[ty*8 + r][k]);
                acc[r][0] = fma2(ad.x, w0.x, acc[r][0]);
                acc[r][1] = fma2(ad.x, w0.y, acc[r][1]);
                acc[r][0] = fma2(ad.y, w1.x, acc[r][0]);
                acc[r][1] = fma2(ad.y, w1.y, acc[r][1]);
            }
        }
        __syncthreads();
    }
    const float4 bv = reinterpret_cast<const float4*>(b)[tx];
#pragma unroll
    for (int r = 0; r < 8; r++) {
        const int row = row0 + ty*8 + r;
        float2 p0 = unpk(acc[r][0]), p1 = unpk(acc[r][1]);
        float4 o;
        o.x = p0.x + bv.x; o.y = p0.y + bv.y;
        o.z = p1.x + bv.z; o.w = p1.y + bv.w;
        if (MODE == 1) { o.x = fsig(o.x); o.y = fsig(o.y); o.z = fsig(o.z); o.w = fsig(o.w); }
        reinterpret_cast<float4*>(dst)[(size_t)row * 32 + tx] = o;
    }
}

// ---------------------------------------------------------------------------
// K4: einsum  pre[i,k,d] = (sum_j left[i,j,d] * right[j,k,d]) * gate[i,k,d]
// Channel-SPLIT: each CTA handles 64 of the 128 channels (half = bId&1), so
// acc drops to 32 u64 -> 2 CTAs/SM (16 warps) for latency hiding.
// Tile 16i x 16k x 64ch, warp = 4i x 8k, lane = one f32x2 channel pair.
// 3-stage cp.async ring with uniform group commits (race-safe, proven R5).
// 8x8 block supertile swizzle on the (i,k) tile index for L2 reuse.
// ---------------------------------------------------------------------------
__global__ __launch_bounds__(256, 2) void einsum_kernel()
{
    __shared__ u64 sL[3][16][32];   // 12 KB
    __shared__ u64 sR[3][16][32];   // 12 KB

    const int t    = threadIdx.x;
    const int lane = t & 31;        // channel pair within the 64-ch half
    const int wid  = t >> 5;
    const int wi   = wid & 3;       // i sub-group (4 rows)
    const int wk   = wid >> 2;      // k sub-group (8 cols)

    const int bId  = blockIdx.x;
    const int half = bId & 1;       // which 64 channels
    const int tile = bId >> 1;      // 0..1023
    const int grp  = tile >> 6;     // 16 supertiles (4x4)
    const int loc  = tile & 63;     // 8x8 within supertile
    const int bi   = ((grp >> 2) << 3) + (loc >> 3);
    const int bk   = ((grp &  3) << 3) + (loc &  7);
    const int i0   = bi * 16, k0 = bk * 16;
    const int ch0  = half * 64;     // float offset of this CTA's channels

    // loader mapping: 256 threads cover 16 rows x 16 16B-chunks per tensor
    const int lrow = t >> 4;         // 0..15
    const int lcol = (t & 15) * 2;   // u64 column (0,2,...,30)

    u64 acc[4][8];
#pragma unroll
    for (int a = 0; a < 4; a++)
#pragma unroll
        for (int c = 0; c < 8; c++) acc[a][c] = 0ull;

    auto issue_stage = [&](int j, int buf) {
        cp16(&sL[buf][lrow][lcol],
             &g_left [((size_t)(i0 + lrow) * NRES + j) * DCH + ch0 + (t & 15) * 4]);
        cp16(&sR[buf][lrow][lcol],
             &g_right[((size_t)j * NRES + (k0 + lrow)) * DCH + ch0 + (t & 15) * 4]);
    };

    issue_stage(0, 0);
    asm volatile("cp.async.commit_group;");
    issue_stage(1, 1);
    asm volatile("cp.async.commit_group;");

    int buf = 0;
    for (int j = 0; j < NRES; j++) {
        // Exactly 2 groups pending here (stages j, j+1); retire stage j.
        asm volatile("cp.async.wait_group 1;");
        __syncthreads();
        if (j + 2 < NRES) {
            int nb = buf + 2; if (nb >= 3) nb -= 3;
            issue_stage(j + 2, nb);
        }
        asm volatile("cp.async.commit_group;");   // uniform group count (tail-safe)
        u64 la[4];
#pragma unroll
        for (int a = 0; a < 4; a++) la[a] = sL[buf][wi*4 + a][lane];
#pragma unroll
        for (int c = 0; c < 8; c++) {
            const u64 rb = sR[buf][wk*8 + c][lane];
#pragma unroll
            for (int a = 0; a < 4; a++) acc[a][c] = fma2(la[a], rb, acc[a][c]);
        }
        if (++buf == 3) buf = 0;
    }

    const u64* __restrict__ G1 = reinterpret_cast<const u64*>(g_gate);
    u64* __restrict__ P1 = reinterpret_cast<u64*>(g_pre);
    const int choff = half * 32 + lane;
#pragma unroll
    for (int a = 0; a < 4; a++) {
        const int i = i0 + wi*4 + a;
#pragma unroll
        for (int c = 0; c < 8; c++) {
            const int k = k0 + wk*8 + c;
            const size_t pos = (size_t)i * NRES + k;
            const u64 gt = G1[pos * 64 + choff];
            P1[pos * 64 + choff] = mul2(acc[a][c], gt);
        }
    }
}

// ---------------------------------------------------------------------------
extern "C" void kernel_launch(void* const* d_in, const int* in_sizes, int n_in,
                              void* d_out, int out_size)
{
    const float* pair = (const float*)d_in[0];
    const float* mask = (const float*)d_in[1];
    const float* ln_g = (const float*)d_in[2];
    const float* ln_b = (const float*)d_in[3];
    const float* w_lp = (const float*)d_in[4];
    const float* b_lp = (const float*)d_in[5];
    const float* w_lg = (const float*)d_in[6];
    const float* b_lg = (const float*)d_in[7];
    const float* w_rp = (const float*)d_in[8];
    const float* b_rp = (const float*)d_in[9];
    const float* w_rg = (const float*)d_in[10];
    const float* b_rg = (const float*)d_in[11];
    const float* w_g  = (const float*)d_in[12];
    const float* b_g  = (const float*)d_in[13];
    const float* w_o  = (const float*)d_in[14];
    const float* b_o  = (const float*)d_in[15];
    float* out = (float*)d_out;

    ln_kernel<<<NPOS / 8, 256>>>(pair, ln_g, ln_b);
    proj_dual<0><<<NPOS / 64, 256>>>(w_lp, b_lp, w_lg, b_lg, mask);
    proj_dual<1><<<NPOS / 64, 256>>>(w_rp, b_rp, w_rg, b_rg, mask);
    proj_single<1><<<NPOS / 64, 256>>>(w_g, b_g, nullptr);
    einsum_kernel<<<2048, 256>>>();
    proj_single<0><<<NPOS / 64, 256>>>(w_o, b_o, out);
}

// round 8
// speedup vs baseline: 2.0210x; 1.3606x over previous
#include <cuda_runtime.h>
#include <cuda_bf16.h>
#include <cstdint>

typedef unsigned long long u64;

#define NRES 512
#define DCH  128
#define NPOS (NRES*NRES)

// Scratch (device globals — no runtime allocation allowed)
__device__ float g_xln  [(size_t)NPOS * DCH];
__device__ float g_left [(size_t)NPOS * DCH];
__device__ float g_right[(size_t)NPOS * DCH];
__device__ float g_gate [(size_t)NPOS * DCH];
__device__ float g_pre  [(size_t)NPOS * DCH];
__device__ float g_pret [(size_t)NPOS * DCH];        // [d][i][k]
__device__ __nv_bfloat16 g_Lh[(size_t)DCH * NPOS];   // [d][i][j]
__device__ __nv_bfloat16 g_Ll[(size_t)DCH * NPOS];
__device__ __nv_bfloat16 g_Rh[(size_t)DCH * NPOS];   // [d][k][j]
__device__ __nv_bfloat16 g_Rl[(size_t)DCH * NPOS];

__device__ __forceinline__ float fsig(float x) { return 1.0f / (1.0f + __expf(-x)); }

__device__ __forceinline__ u64 fma2(u64 a, u64 b, u64 c) {
    u64 d;
    asm("fma.rn.f32x2 %0, %1, %2, %3;" : "=l"(d) : "l"(a), "l"(b), "l"(c));
    return d;
}
__device__ __forceinline__ u64 dup2(float a) {
    u64 r;
    asm("mov.b64 %0, {%1, %1};" : "=l"(r) : "f"(a));
    return r;
}
__device__ __forceinline__ float2 unpk(u64 v) {
    float2 f;
    asm("mov.b64 {%0, %1}, %2;" : "=f"(f.x), "=f"(f.y) : "l"(v));
    return f;
}
__device__ __forceinline__ void cp16(void* s, const void* g) {
    unsigned sa = (unsigned)__cvta_generic_to_shared(s);
    asm volatile("cp.async.cg.shared.global [%0], [%1], 16;" :: "r"(sa), "l"(g));
}

// ---- mma.sync / ldmatrix (sm_80-class PTX: compiles on plain sm_103) ------
__device__ __forceinline__ void ldsm_x4(uint32_t* r, uint32_t addr) {
    asm volatile("ldmatrix.sync.aligned.m8n8.x4.shared.b16 {%0,%1,%2,%3}, [%4];"
        : "=r"(r[0]), "=r"(r[1]), "=r"(r[2]), "=r"(r[3]) : "r"(addr));
}
__device__ __forceinline__ void ldsm_x2(uint32_t* r, uint32_t addr) {
    asm volatile("ldmatrix.sync.aligned.m8n8.x2.shared.b16 {%0,%1}, [%2];"
        : "=r"(r[0]), "=r"(r[1]) : "r"(addr));
}
__device__ __forceinline__ void mma16816(float* c, const uint32_t* a, const uint32_t* b) {
    asm volatile("mma.sync.aligned.m16n8k16.row.col.f32.bf16.bf16.f32 "
        "{%0,%1,%2,%3}, {%4,%5,%6,%7}, {%8,%9}, {%0,%1,%2,%3};"
        : "+f"(c[0]), "+f"(c[1]), "+f"(c[2]), "+f"(c[3])
        : "r"(a[0]), "r"(a[1]), "r"(a[2]), "r"(a[3]), "r"(b[0]), "r"(b[1]));
}

__device__ __forceinline__ void bsplit(float v, __nv_bfloat16& h, __nv_bfloat16& l) {
    h = __float2bfloat16(v);
    l = __float2bfloat16(v - __bfloat162float(h));
}
__device__ __forceinline__ uint32_t pack2(__nv_bfloat16 a, __nv_bfloat16 b) {
    __nv_bfloat162 p(a, b);
    return *reinterpret_cast<uint32_t*>(&p);
}

// ---------------------------------------------------------------------------
// K1: LayerNorm over D=128.
// ---------------------------------------------------------------------------
__global__ void ln_kernel(const float* __restrict__ pair,
                          const float* __restrict__ lng,
                          const float* __restrict__ lnb)
{
    const int lane = threadIdx.x & 31;
    const int row  = blockIdx.x * 8 + (threadIdx.x >> 5);
    const float4 v = reinterpret_cast<const float4*>(pair)[(size_t)row * 32 + lane];
    float s = v.x + v.y + v.z + v.w;
    float q = v.x*v.x + v.y*v.y + v.z*v.z + v.w*v.w;
#pragma unroll
    for (int o = 16; o > 0; o >>= 1) {
        s += __shfl_xor_sync(0xffffffffu, s, o);
        q += __shfl_xor_sync(0xffffffffu, q, o);
    }
    const float mean = s * (1.0f / 128.0f);
    const float var  = q * (1.0f / 128.0f) - mean * mean;
    const float rs   = rsqrtf(var + 1e-5f);
    const float4 g4 = reinterpret_cast<const float4*>(lng)[lane];
    const float4 b4 = reinterpret_cast<const float4*>(lnb)[lane];
    float4 o4;
    o4.x = (v.x - mean) * rs * g4.x + b4.x;
    o4.y = (v.y - mean) * rs * g4.y + b4.y;
    o4.z = (v.z - mean) * rs * g4.z + b4.z;
    o4.w = (v.w - mean) * rs * g4.w + b4.w;
    reinterpret_cast<float4*>(g_xln)[(size_t)row * 32 + lane] = o4;
}

// ---------------------------------------------------------------------------
// K2: dual projection: dst = (x@Wp+bp)*sig(x@Wg+bg)*mask  (R6, proven)
// ---------------------------------------------------------------------------
template<int DST>
__global__ __launch_bounds__(256, 2) void proj_dual(
    const float* __restrict__ wp, const float* __restrict__ bp,
    const float* __restrict__ wg, const float* __restrict__ bg,
    const float* __restrict__ mask)
{
    __shared__ u64    sAd[64][16];
    __shared__ float4 sWp[16][32];
    __shared__ float4 sWq[16][32];
    float* __restrict__ dst = (DST == 0) ? g_left : g_right;

    const int t    = threadIdx.x;
    const int row0 = blockIdx.x * 64;
    const int tx   = t & 31;
    const int ty   = t >> 5;

    u64 aP[8][2], aG[8][2];
#pragma unroll
    for (int r = 0; r < 8; r++) {
        aP[r][0] = aP[r][1] = 0ull;
        aG[r][0] = aG[r][1] = 0ull;
    }

    for (int kc = 0; kc < 8; kc++) {
#pragma unroll
        for (int q = 0; q < 4; q++) {
            int idx = t + q * 256;
            int row = idx >> 4, kk = idx & 15;
            float a = g_xln[(size_t)(row0 + row) * DCH + kc * 16 + kk];
            sAd[row][kk] = dup2(a);
        }
#pragma unroll
        for (int q = 0; q < 2; q++) {
            int idx = t + q * 256;
            int r = idx >> 5, c = idx & 31;
            sWp[r][c] = reinterpret_cast<const float4*>(wp)[(size_t)(kc*16 + r)*32 + c];
            sWq[r][c] = reinterpret_cast<const float4*>(wg)[(size_t)(kc*16 + r)*32 + c];
        }
        __syncthreads();
#pragma unroll
        for (int k = 0; k < 16; k += 2) {
            const ulonglong2 wp0 = *reinterpret_cast<const ulonglong2*>(&sWp[k  ][tx]);
            const ulonglong2 wp1 = *reinterpret_cast<const ulonglong2*>(&sWp[k+1][tx]);
            const ulonglong2 wq0 = *reinterpret_cast<const ulonglong2*>(&sWq[k  ][tx]);
            const ulonglong2 wq1 = *reinterpret_cast<const ulonglong2*>(&sWq[k+1][tx]);
#pragma unroll
            for (int r = 0; r < 8; r++) {
                const ulonglong2 ad = *reinterpret_cast<const ulonglong2*>(&sAd[ty*8 + r][k]);
                aP[r][0] = fma2(ad.x, wp0.x, aP[r][0]);
                aP[r][1] = fma2(ad.x, wp0.y, aP[r][1]);
                aP[r][0] = fma2(ad.y, wp1.x, aP[r][0]);
                aP[r][1] = fma2(ad.y, wp1.y, aP[r][1]);
                aG[r][0] = fma2(ad.x, wq0.x, aG[r][0]);
                aG[r][1] = fma2(ad.x, wq0.y, aG[r][1]);
                aG[r][0] = fma2(ad.y, wq1.x, aG[r][0]);
                aG[r][1] = fma2(ad.y, wq1.y, aG[r][1]);
            }
        }
        __syncthreads();
    }
    const float4 bpv = reinterpret_cast<const float4*>(bp)[tx];
    const float4 bqv = reinterpret_cast<const float4*>(bg)[tx];
#pragma unroll
    for (int r = 0; r < 8; r++) {
        const int row = row0 + ty*8 + r;
        const float m = mask[row];
        float2 p0 = unpk(aP[r][0]), p1 = unpk(aP[r][1]);
        float2 g0 = unpk(aG[r][0]), g1 = unpk(aG[r][1]);
        float4 o;
        o.x = (p0.x + bpv.x) * fsig(g0.x + bqv.x) * m;
        o.y = (p0.y + bpv.y) * fsig(g0.y + bqv.y) * m;
        o.z = (p1.x + bpv.z) * fsig(g1.x + bqv.z) * m;
        o.w = (p1.y + bpv.w) * fsig(g1.y + bqv.w) * m;
        reinterpret_cast<float4*>(dst)[(size_t)row * 32 + tx] = o;
    }
}

// ---------------------------------------------------------------------------
// K3: single projection (R6, proven).
// ---------------------------------------------------------------------------
template<int MODE>
__global__ __launch_bounds__(256, 2) void proj_single(
    const float* __restrict__ w, const float* __restrict__ b,
    float* __restrict__ out)
{
    __shared__ u64    sAd[64][16];
    __shared__ float4 sW[16][32];
    const float* __restrict__ src = (MODE == 1) ? g_xln : g_pre;
    float* __restrict__ dst = (MODE == 1) ? g_gate : out;

    const int t    = threadIdx.x;
    const int row0 = blockIdx.x * 64;
    const int tx   = t & 31;
    const int ty   = t >> 5;

    u64 acc[8][2];
#pragma unroll
    for (int r = 0; r < 8; r++) acc[r][0] = acc[r][1] = 0ull;

    for (int kc = 0; kc < 8; kc++) {
#pragma unroll
        for (int q = 0; q < 4; q++) {
            int idx = t + q * 256;
            int row = idx >> 4, kk = idx & 15;
            float a = src[(size_t)(row0 + row) * DCH + kc * 16 + kk];
            sAd[row][kk] = dup2(a);
        }
#pragma unroll
        for (int q = 0; q < 2; q++) {
            int idx = t + q * 256;
            sW[idx >> 5][idx & 31] =
                reinterpret_cast<const float4*>(w)[(size_t)(kc*16 + (idx>>5))*32 + (idx&31)];
        }
        __syncthreads();
#pragma unroll
        for (int k = 0; k < 16; k += 2) {
            const ulonglong2 w0 = *reinterpret_cast<const ulonglong2*>(&sW[k  ][tx]);
            const ulonglong2 w1 = *reinterpret_cast<const ulonglong2*>(&sW[k+1][tx]);
#pragma unroll
            for (int r = 0; r < 8; r++) {
                const ulonglong2 ad = *reinterpret_cast<const ulonglong2*>(&sAd[ty*8 + r][k]);
                acc[r][0] = fma2(ad.x, w0.x, acc[r][0]);
                acc[r][1] = fma2(ad.x, w0.y, acc[r][1]);
                acc[r][0] = fma2(ad.y, w1.x, acc[r][0]);
                acc[r][1] = fma2(ad.y, w1.y, acc[r][1]);
            }
        }
        __syncthreads();
    }
    const float4 bv = reinterpret_cast<const float4*>(b)[tx];
#pragma unroll
    for (int r = 0; r < 8; r++) {
        const int row = row0 + ty*8 + r;
        float2 p0 = unpk(acc[r][0]), p1 = unpk(acc[r][1]);
        float4 o;
        o.x = p0.x + bv.x; o.y = p0.y + bv.y;
        o.z = p1.x + bv.z; o.w = p1.y + bv.w;
        if (MODE == 1) { o.x = fsig(o.x); o.y = fsig(o.y); o.z = fsig(o.z); o.w = fsig(o.w); }
        reinterpret_cast<float4*>(dst)[(size_t)row * 32 + tx] = o;
    }
}

// ---------------------------------------------------------------------------
// T1: split left[pos][d] -> Lh/Ll[d][pos] bf16 (channel transpose only).
// ---------------------------------------------------------------------------
__global__ __launch_bounds__(256) void splitL_kernel()
{
    __shared__ float sX[32][128];
    const int t = threadIdx.x;
    const size_t pos0 = (size_t)blockIdx.x * 32;
#pragma unroll
    for (int q = 0; q < 4; q++) {
        int idx = t + q * 256;
        int row = idx >> 5, c4 = idx & 31;
        float4 v = reinterpret_cast<const float4*>(g_left)[(pos0 + row) * 32 + c4];
        *reinterpret_cast<float4*>(&sX[row][c4 * 4]) = v;
    }
    __syncthreads();
    const int d = t >> 1, h = (t & 1) * 16;
    uint32_t wh[8], wl[8];
#pragma unroll
    for (int q = 0; q < 8; q++) {
        __nv_bfloat16 h0, l0, h1, l1;
        bsplit(sX[h + 2*q    ][d], h0, l0);
        bsplit(sX[h + 2*q + 1][d], h1, l1);
        wh[q] = pack2(h0, h1);
        wl[q] = pack2(l0, l1);
    }
    const size_t ob = (size_t)d * NPOS + pos0 + h;
    *reinterpret_cast<uint4*>(&g_Lh[ob])     = make_uint4(wh[0], wh[1], wh[2], wh[3]);
    *reinterpret_cast<uint4*>(&g_Lh[ob + 8]) = make_uint4(wh[4], wh[5], wh[6], wh[7]);
    *reinterpret_cast<uint4*>(&g_Ll[ob])     = make_uint4(wl[0], wl[1], wl[2], wl[3]);
    *reinterpret_cast<uint4*>(&g_Ll[ob + 8]) = make_uint4(wl[4], wl[5], wl[6], wl[7]);
}

// ---------------------------------------------------------------------------
// T2: split+transpose right[(j,k)][d] -> Rh/Rl[d][k][j] bf16.
// ---------------------------------------------------------------------------
__global__ __launch_bounds__(256) void splitR_kernel()
{
    __shared__ float sY[32 * 8 * 33];   // [k][d][j], j padded to 33
    const int t = threadIdx.x;
    const int b = blockIdx.x;           // 16 dg x 16 kb x 16 jb
    const int dg = b >> 8;
    const int kb = (b >> 4) & 15;
    const int jb = b & 15;
    const int j0 = jb * 32, k0 = kb * 32, d0 = dg * 8;
#pragma unroll
    for (int q = 0; q < 8; q++) {
        int idx = t + q * 256;          // 0..2047
        int j   = idx >> 6;
        int rem = idx & 63;
        int k   = rem >> 1;
        int dq  = rem & 1;
        float4 v = reinterpret_cast<const float4*>(g_right)[
            ((size_t)(j0 + j) * NRES + k0 + k) * 32 + (d0 >> 2) + dq];
        float* dst = &sY[(k * 8 + dq * 4) * 33 + j];
        dst[0]  = v.x; dst[33] = v.y; dst[66] = v.z; dst[99] = v.w;
    }
    __syncthreads();
    const int d = t >> 5, k = t & 31;
    const float* src = &sY[(k * 8 + d) * 33];
    uint32_t wh[16], wl[16];
#pragma unroll
    for (int q = 0; q < 16; q++) {
        __nv_bfloat16 h0, l0, h1, l1;
        bsplit(src[2*q    ], h0, l0);
        bsplit(src[2*q + 1], h1, l1);
        wh[q] = pack2(h0, h1);
        wl[q] = pack2(l0, l1);
    }
    const size_t ob = ((size_t)(d0 + d) * NRES + k0 + k) * NRES + j0;
#pragma unroll
    for (int q = 0; q < 4; q++) {
        *reinterpret_cast<uint4*>(&g_Rh[ob + q * 8]) =
            make_uint4(wh[q*4], wh[q*4+1], wh[q*4+2], wh[q*4+3]);
        *reinterpret_cast<uint4*>(&g_Rl[ob + q * 8]) =
            make_uint4(wl[q*4], wl[q*4+1], wl[q*4+2], wl[q*4+3]);
    }
}

// ---------------------------------------------------------------------------
// K4: einsum via mma.sync bf16 (hi/lo split, fp32 acc).
// Per CTA: channel d, 128i x 64k tile. K=512 in 16 stages of 32j.
// 3-stage cp.async ring, uniform commits. Smem rows padded to 80B
// (5 mod 8 -> ldmatrix conflict-free). 8 warps = 4M x 2N, warp=32x32,
// mma tiles 2m x 4n, 3 products each: C += Ah*Bh + Ah*Bl + Al*Bh.
// ---------------------------------------------------------------------------
#define EM_RS     80                        // smem row stride bytes (40 bf16)
#define EM_A_T    (128 * EM_RS)             // 10240 B
#define EM_B_T    (64 * EM_RS)              // 5120 B
#define EM_STAGE  (2 * EM_A_T + 2 * EM_B_T) // 30720 B
#define EM_SMEM   (3 * EM_STAGE)            // 92160 B

__global__ __launch_bounds__(256, 2) void einsum_mma_kernel()
{
    extern __shared__ char smem[];
    const uint32_t sbase = (uint32_t)__cvta_generic_to_shared(smem);
    const int t    = threadIdx.x;
    const int lane = t & 31;
    const int wid  = t >> 5;
    const int wm   = wid & 3;    // 4 M groups of 32 rows
    const int wn   = wid >> 2;   // 2 N groups of 32 cols

    const int bid = blockIdx.x;
    const int d   = bid >> 5;
    const int i0  = ((bid >> 3) & 3) * 128;
    const int k0  = (bid & 7) * 64;

    const __nv_bfloat16* __restrict__ pLh = g_Lh + (size_t)d * NPOS + (size_t)i0 * NRES;
    const __nv_bfloat16* __restrict__ pLl = g_Ll + (size_t)d * NPOS + (size_t)i0 * NRES;
    const __nv_bfloat16* __restrict__ pRh = g_Rh + (size_t)d * NPOS + (size_t)k0 * NRES;
    const __nv_bfloat16* __restrict__ pRl = g_Rl + (size_t)d * NPOS + (size_t)k0 * NRES;

    float acc[2][4][4];
#pragma unroll
    for (int mt = 0; mt < 2; mt++)
#pragma unroll
        for (int nt = 0; nt < 4; nt++)
#pragma unroll
            for (int c = 0; c < 4; c++) acc[mt][nt][c] = 0.0f;

    // fill stage s (j0s = s*32) into buffer s%3
    auto fill = [&](int s) {
        const int buf = s % 3;
        char* base = smem + buf * EM_STAGE;
        const int j0s = s * 32;
        {   // Lh: 512 chunks (2 rounds), Ll: 512
            int c0 = t, c1 = t + 256;
            int r0 = c0 >> 2, r1 = c1 >> 2, col0 = c0 & 3, col1 = c1 & 3;
            cp16(base + r0 * EM_RS + col0 * 16,
                 pLh + (size_t)r0 * NRES + j0s + col0 * 8);
            cp16(base + r1 * EM_RS + col1 * 16,
                 pLh + (size_t)r1 * NRES + j0s + col1 * 8);
            cp16(base + EM_A_T + r0 * EM_RS + col0 * 16,
                 pLl + (size_t)r0 * NRES + j0s + col0 * 8);
            cp16(base + EM_A_T + r1 * EM_RS + col1 * 16,
                 pLl + (size_t)r1 * NRES + j0s + col1 * 8);
        }
        {   // Rh: 256 chunks, Rl: 256
            int r = t >> 2, col = t & 3;
            cp16(base + 2 * EM_A_T + r * EM_RS + col * 16,
                 pRh + (size_t)r * NRES + j0s + col * 8);
            cp16(base + 2 * EM_A_T + EM_B_T + r * EM_RS + col * 16,
                 pRl + (size_t)r * NRES + j0s + col * 8);
        }
    };

    fill(0); asm volatile("cp.async.commit_group;");
    fill(1); asm volatile("cp.async.commit_group;");

    // per-lane invariant pieces of ldmatrix addresses
    const uint32_t aOff = (uint32_t)((wm * 32 + ((lane >> 3) & 1) * 8 + (lane & 7)) * EM_RS
                                     + ((lane >> 4) << 4));
    const uint32_t bOff = (uint32_t)((wn * 32 + (lane & 7)) * EM_RS
                                     + (((lane >> 3) & 1) << 4));

    for (int s = 0; s < 16; s++) {
        asm volatile("cp.async.wait_group 1;");
        __syncthreads();                      // stage s visible; all warps done with s-1
        if (s + 2 < 16) fill(s + 2);
        asm volatile("cp.async.commit_group;");   // uniform group count (tail-safe)

        const uint32_t sb  = sbase + (s % 3) * EM_STAGE;
        const uint32_t aHb = sb, aLb = sb + EM_A_T;
        const uint32_t bHb = sb + 2 * EM_A_T, bLb = bHb + EM_B_T;

#pragma unroll
        for (int kh = 0; kh < 2; kh++) {
            const uint32_t kb = kh * 32;      // 16 bf16 = 32 bytes
            uint32_t aH[2][4], aL[2][4];
            ldsm_x4(aH[0], aHb + aOff + kb);
            ldsm_x4(aH[1], aHb + aOff + 16 * EM_RS + kb);
            ldsm_x4(aL[0], aLb + aOff + kb);
            ldsm_x4(aL[1], aLb + aOff + 16 * EM_RS + kb);
#pragma unroll
            for (int nt = 0; nt < 4; nt++) {
                uint32_t bH[2], bL[2];
                ldsm_x2(bH, bHb + bOff + nt * 8 * EM_RS + kb);
                ldsm_x2(bL, bLb + bOff + nt * 8 * EM_RS + kb);
#pragma unroll
                for (int mt = 0; mt < 2; mt++) {
                    mma16816(acc[mt][nt], aH[mt], bH);
                    mma16816(acc[mt][nt], aH[mt], bL);
                    mma16816(acc[mt][nt], aL[mt], bH);
                }
            }
        }
    }

    // Epilogue: write pre_t[d][i][k]
    float* __restrict__ pOut = g_pret + (size_t)d * NPOS;
    const int g  = lane >> 2;
    const int kc = (lane & 3) * 2;
#pragma unroll
    for (int mt = 0; mt < 2; mt++) {
#pragma unroll
        for (int nt = 0; nt < 4; nt++) {
            const int i = i0 + wm * 32 + mt * 16 + g;
            const int k = k0 + wn * 32 + nt * 8 + kc;
            *reinterpret_cast<float2*>(&pOut[(size_t)i * NRES + k]) =
                make_float2(acc[mt][nt][0], acc[mt][nt][1]);
            *reinterpret_cast<float2*>(&pOut[(size_t)(i + 8) * NRES + k]) =
                make_float2(acc[mt][nt][2], acc[mt][nt][3]);
        }
    }
}

// ---------------------------------------------------------------------------
// T3: g_pre[pos][d] = g_pret[d][pos] * g_gate[pos][d]
// ---------------------------------------------------------------------------
__global__ __launch_bounds__(256) void fuse_gate_kernel()
{
    __shared__ float sP[32][128];
    const int t = threadIdx.x;
    const size_t pos0 = (size_t)blockIdx.x * 32;
    const int d = t >> 1, h = (t & 1) * 16;
#pragma unroll
    for (int q = 0; q < 4; q++) {
        float4 v = reinterpret_cast<const float4*>(g_pret)[
            ((size_t)d * NPOS + pos0 + h) / 4 + q];
        sP[h + q*4 + 0][d] = v.x;
        sP[h + q*4 + 1][d] = v.y;
        sP[h + q*4 + 2][d] = v.z;
        sP[h + q*4 + 3][d] = v.w;
    }
    __syncthreads();
#pragma unroll
    for (int q = 0; q < 4; q++) {
        int idx = t + q * 256;
        int row = idx >> 5, c4 = idx & 31;
        float4 p = *reinterpret_cast<float4*>(&sP[row][c4 * 4]);
        float4 g = reinterpret_cast<const float4*>(g_gate)[(pos0 + row) * 32 + c4];
        p.x *= g.x; p.y *= g.y; p.z *= g.z; p.w *= g.w;
        reinterpret_cast<float4*>(g_pre)[(pos0 + row) * 32 + c4] = p;
    }
}

// ---------------------------------------------------------------------------
extern "C" void kernel_launch(void* const* d_in, const int* in_sizes, int n_in,
                              void* d_out, int out_size)
{
    (void)in_sizes; (void)n_in; (void)out_size;
    const float* pair = (const float*)d_in[0];
    const float* mask = (const float*)d_in[1];
    const float* ln_g = (const float*)d_in[2];
    const float* ln_b = (const float*)d_in[3];
    const float* w_lp = (const float*)d_in[4];
    const float* b_lp = (const float*)d_in[5];
    const float* w_lg = (const float*)d_in[6];
    const float* b_lg = (const float*)d_in[7];
    const float* w_rp = (const float*)d_in[8];
    const float* b_rp = (const float*)d_in[9];
    const float* w_rg = (const float*)d_in[10];
    const float* b_rg = (const float*)d_in[11];
    const float* w_g  = (const float*)d_in[12];
    const float* b_g  = (const float*)d_in[13];
    const float* w_o  = (const float*)d_in[14];
    const float* b_o  = (const float*)d_in[15];
    float* out = (float*)d_out;

    cudaFuncSetAttribute(einsum_mma_kernel,
                         cudaFuncAttributeMaxDynamicSharedMemorySize, EM_SMEM);

    ln_kernel<<<NPOS / 8, 256>>>(pair, ln_g, ln_b);
    proj_dual<0><<<NPOS / 64, 256>>>(w_lp, b_lp, w_lg, b_lg, mask);
    proj_dual<1><<<NPOS / 64, 256>>>(w_rp, b_rp, w_rg, b_rg, mask);
    proj_single<1><<<NPOS / 64, 256>>>(w_g, b_g, nullptr);
    splitL_kernel<<<NPOS / 32, 256>>>();
    splitR_kernel<<<4096, 256>>>();
    einsum_mma_kernel<<<4096, 256, EM_SMEM>>>();
    fuse_gate_kernel<<<NPOS / 32, 256>>>();
    proj_single<0><<<NPOS / 64, 256>>>(w_o, b_o, out);
}

// round 9
// speedup vs baseline: 3.1452x; 1.5563x over previous
#include <cuda_runtime.h>
#include <cuda_bf16.h>
#include <cstdint>

#define NRES 512
#define DCH  128
#define NPOS (NRES*NRES)

// Scratch (device globals — no runtime allocation allowed)
__device__ float g_left [(size_t)NPOS * DCH];
__device__ float g_right[(size_t)NPOS * DCH];
__device__ float g_gate [(size_t)NPOS * DCH];
__device__ float g_pret [(size_t)NPOS * DCH];        // [d][i][k]
__device__ __nv_bfloat16 g_Xh[(size_t)NPOS * DCH];   // LN(x) split, [pos][d]
__device__ __nv_bfloat16 g_Xl[(size_t)NPOS * DCH];
__device__ __nv_bfloat16 g_Lh[(size_t)DCH * NPOS];   // [d][i][j]; later pre-split [pos][d]
__device__ __nv_bfloat16 g_Ll[(size_t)DCH * NPOS];
__device__ __nv_bfloat16 g_Rh[(size_t)DCH * NPOS];   // [d][k][j]
__device__ __nv_bfloat16 g_Rl[(size_t)DCH * NPOS];
__device__ __nv_bfloat16 g_Wth[6 * DCH * DCH];       // W^T hi, [widx][n][k]
__device__ __nv_bfloat16 g_Wtl[6 * DCH * DCH];       // W^T lo

__device__ __forceinline__ float fsig(float x) { return 1.0f / (1.0f + __expf(-x)); }

__device__ __forceinline__ void cp16(void* s, const void* g) {
    unsigned sa = (unsigned)__cvta_generic_to_shared(s);
    asm volatile("cp.async.cg.shared.global [%0], [%1], 16;" :: "r"(sa), "l"(g));
}

// ---- mma.sync / ldmatrix (sm_80-class PTX: compiles on plain sm_103) ------
__device__ __forceinline__ void ldsm_x4(uint32_t* r, uint32_t addr) {
    asm volatile("ldmatrix.sync.aligned.m8n8.x4.shared.b16 {%0,%1,%2,%3}, [%4];"
        : "=r"(r[0]), "=r"(r[1]), "=r"(r[2]), "=r"(r[3]) : "r"(addr));
}
__device__ __forceinline__ void ldsm_x2(uint32_t* r, uint32_t addr) {
    asm volatile("ldmatrix.sync.aligned.m8n8.x2.shared.b16 {%0,%1}, [%2];"
        : "=r"(r[0]), "=r"(r[1]) : "r"(addr));
}
__device__ __forceinline__ void mma16816(float* c, const uint32_t* a, const uint32_t* b) {
    asm volatile("mma.sync.aligned.m16n8k16.row.col.f32.bf16.bf16.f32 "
        "{%0,%1,%2,%3}, {%4,%5,%6,%7}, {%8,%9}, {%0,%1,%2,%3};"
        : "+f"(c[0]), "+f"(c[1]), "+f"(c[2]), "+f"(c[3])
        : "r"(a[0]), "r"(a[1]), "r"(a[2]), "r"(a[3]), "r"(b[0]), "r"(b[1]));
}
// C += Ah*Bh + Ah*Bl + Al*Bh   (bf16 hi/lo split product)
__device__ __forceinline__ void mma3(float* c, const uint32_t* aH, const uint32_t* aL,
                                     uint32_t bh0, uint32_t bh1,
                                     uint32_t bl0, uint32_t bl1) {
    uint32_t b[2];
    b[0] = bh0; b[1] = bh1; mma16816(c, aH, b);
    b[0] = bl0; b[1] = bl1; mma16816(c, aH, b);
    b[0] = bh0; b[1] = bh1; mma16816(c, aL, b);
}

__device__ __forceinline__ void bsplit(float v, __nv_bfloat16& h, __nv_bfloat16& l) {
    h = __float2bfloat16(v);
    l = __float2bfloat16(v - __bfloat162float(h));
}
__device__ __forceinline__ uint32_t pack2(__nv_bfloat16 a, __nv_bfloat16 b) {
    __nv_bfloat162 p(a, b);
    return *reinterpret_cast<uint32_t*>(&p);
}

// ---------------------------------------------------------------------------
// K0: weight prep — W[k][n] -> Wt_h/Wt_l[n][k] bf16. One block per matrix.
// ---------------------------------------------------------------------------
__global__ void prep_weights(const float* w0, const float* w1, const float* w2,
                             const float* w3, const float* w4, const float* w5)
{
    const float* srcs[6] = {w0, w1, w2, w3, w4, w5};
    const float* src = srcs[blockIdx.x];
    const int base = blockIdx.x * DCH * DCH;
    for (int idx = threadIdx.x; idx < DCH * DCH; idx += blockDim.x) {
        int k = idx >> 7, n = idx & 127;
        __nv_bfloat16 h, l;
        bsplit(src[idx], h, l);
        g_Wth[base + n * DCH + k] = h;
        g_Wtl[base + n * DCH + k] = l;
    }
}

// ---------------------------------------------------------------------------
// K1: LayerNorm over D=128 -> Xh/Xl bf16 [pos][d].
// ---------------------------------------------------------------------------
__global__ void ln_split_kernel(const float* __restrict__ pair,
                                const float* __restrict__ lng,
                                const float* __restrict__ lnb)
{
    const int lane = threadIdx.x & 31;
    const int row  = blockIdx.x * 8 + (threadIdx.x >> 5);
    const float4 v = reinterpret_cast<const float4*>(pair)[(size_t)row * 32 + lane];
    float s = v.x + v.y + v.z + v.w;
    float q = v.x*v.x + v.y*v.y + v.z*v.z + v.w*v.w;
#pragma unroll
    for (int o = 16; o > 0; o >>= 1) {
        s += __shfl_xor_sync(0xffffffffu, s, o);
        q += __shfl_xor_sync(0xffffffffu, q, o);
    }
    const float mean = s * (1.0f / 128.0f);
    const float var  = q * (1.0f / 128.0f) - mean * mean;
    const float rs   = rsqrtf(var + 1e-5f);
    const float4 g4 = reinterpret_cast<const float4*>(lng)[lane];
    const float4 b4 = reinterpret_cast<const float4*>(lnb)[lane];
    float o0 = (v.x - mean) * rs * g4.x + b4.x;
    float o1 = (v.y - mean) * rs * g4.y + b4.y;
    float o2 = (v.z - mean) * rs * g4.z + b4.z;
    float o3 = (v.w - mean) * rs * g4.w + b4.w;
    __nv_bfloat16 h0,l0,h1,l1,h2,l2,h3,l3;
    bsplit(o0,h0,l0); bsplit(o1,h1,l1); bsplit(o2,h2,l2); bsplit(o3,h3,l3);
    uint2 hv = make_uint2(pack2(h0,h1), pack2(h2,h3));
    uint2 lv = make_uint2(pack2(l0,l1), pack2(l2,l3));
    *reinterpret_cast<uint2*>(&g_Xh[(size_t)row * DCH + lane * 4]) = hv;
    *reinterpret_cast<uint2*>(&g_Xl[(size_t)row * DCH + lane * 4]) = lv;
}

// ---------------------------------------------------------------------------
// Projection GEMMs on mma.sync. M tile 64 x N 128, K=128 in 4 stages of 32.
// 8 warps = 4M x 2N, warp = 16 rows x 64 cols. 2-buffer ring; fill(s+2) is
// issued AFTER the post-compute barrier (buffer s&1 free), uniform commits.
// ---------------------------------------------------------------------------
#define PJ_RS      80
#define PJ_A_T     (64 * PJ_RS)               // 5120
#define PJ_B_T     (128 * PJ_RS)              // 10240
#define PJ_STAGE_D (2*PJ_A_T + 4*PJ_B_T)      // 51200
#define PJ_SMEM_D  (2 * PJ_STAGE_D)           // 102400
#define PJ_STAGE_S (2*PJ_A_T + 2*PJ_B_T)      // 30720
#define PJ_SMEM_S  (2 * PJ_STAGE_S)           // 61440

// dual: dst = (X@Wp + bp) * sigmoid(X@Wg + bg) * mask;  DST 0->left, 1->right
template<int WP, int WG, int DST>
__global__ __launch_bounds__(256, 2) void proj_dual_mma(
    const float* __restrict__ bp, const float* __restrict__ bg,
    const float* __restrict__ mask)
{
    extern __shared__ char smem[];
    const uint32_t sbase = (uint32_t)__cvta_generic_to_shared(smem);
    const int t = threadIdx.x, lane = t & 31, wid = t >> 5;
    const int wm = wid & 3, wn = wid >> 2;
    const int row0 = blockIdx.x * 64;
    float* __restrict__ dst = DST ? g_right : g_left;

    const __nv_bfloat16* __restrict__ wph = g_Wth + WP * (DCH*DCH);
    const __nv_bfloat16* __restrict__ wpl = g_Wtl + WP * (DCH*DCH);
    const __nv_bfloat16* __restrict__ wgh = g_Wth + WG * (DCH*DCH);
    const __nv_bfloat16* __restrict__ wgl = g_Wtl + WG * (DCH*DCH);

    float accP[8][4], accG[8][4];
#pragma unroll
    for (int nt = 0; nt < 8; nt++)
#pragma unroll
        for (int c = 0; c < 4; c++) { accP[nt][c] = 0.f; accG[nt][c] = 0.f; }

    auto fill = [&](int s) {
        char* base = smem + (s & 1) * PJ_STAGE_D;
#pragma unroll
        for (int q = 0; q < 2; q++) {           // A: Xh, Xl
            int c = t + q * 256;
            int hl = c >> 8, row = (c >> 2) & 63, col = c & 3;
            const __nv_bfloat16* src = hl ? g_Xl : g_Xh;
            cp16(base + hl * PJ_A_T + row * PJ_RS + col * 16,
                 src + (size_t)(row0 + row) * DCH + s * 32 + col * 8);
        }
        const __nv_bfloat16* wsrc[4] = {wph, wpl, wgh, wgl};
#pragma unroll
        for (int q = 0; q < 8; q++) {           // B: ph, pl, gh, gl
            int c = t + q * 256;
            int m = c >> 9, n = (c >> 2) & 127, col = c & 3;
            cp16(base + 2 * PJ_A_T + m * PJ_B_T + n * PJ_RS + col * 16,
                 wsrc[m] + n * DCH + s * 32 + col * 8);
        }
    };

    fill(0); asm volatile("cp.async.commit_group;");
    fill(1); asm volatile("cp.async.commit_group;");

    const uint32_t aOff = (uint32_t)((wm * 16 + (lane & 15)) * PJ_RS + ((lane >> 4) << 4));
    const uint32_t bOff = (uint32_t)((wn * 64 + (lane & 15)) * PJ_RS + ((lane >> 4) << 4));

    for (int s = 0; s < 4; s++) {
        asm volatile("cp.async.wait_group 1;");
        __syncthreads();
        const uint32_t sb = sbase + (s & 1) * PJ_STAGE_D;
#pragma unroll
        for (int kh = 0; kh < 2; kh++) {
            uint32_t aH[4], aL[4];
            ldsm_x4(aH, sb + aOff + kh * 32);
            ldsm_x4(aL, sb + PJ_A_T + aOff + kh * 32);
#pragma unroll
            for (int ntp = 0; ntp < 4; ntp++) {
                const uint32_t bo = bOff + ntp * 16 * PJ_RS + kh * 32;
                uint32_t pH[4], pL[4], gH[4], gL[4];
                ldsm_x4(pH, sb + 2*PJ_A_T + bo);
                ldsm_x4(pL, sb + 2*PJ_A_T + PJ_B_T + bo);
                ldsm_x4(gH, sb + 2*PJ_A_T + 2*PJ_B_T + bo);
                ldsm_x4(gL, sb + 2*PJ_A_T + 3*PJ_B_T + bo);
                mma3(accP[2*ntp  ], aH, aL, pH[0], pH[2], pL[0], pL[2]);
                mma3(accP[2*ntp+1], aH, aL, pH[1], pH[3], pL[1], pL[3]);
                mma3(accG[2*ntp  ], aH, aL, gH[0], gH[2], gL[0], gL[2]);
                mma3(accG[2*ntp+1], aH, aL, gH[1], gH[3], gL[1], gL[3]);
            }
        }
        __syncthreads();                 // all warps done reading buffer s&1
        if (s + 2 < 4) fill(s + 2);
        asm volatile("cp.async.commit_group;");
    }

    const int g  = lane >> 2;
    const int kc = (lane & 3) * 2;
    const int ra = row0 + wm * 16 + g, rb = ra + 8;
    const float ma = mask[ra], mb = mask[rb];
#pragma unroll
    for (int nt = 0; nt < 8; nt++) {
        const int col = wn * 64 + nt * 8 + kc;
        const float bp0 = bp[col], bp1 = bp[col + 1];
        const float bg0 = bg[col], bg1 = bg[col + 1];
        float2 oa, ob;
        oa.x = (accP[nt][0] + bp0) * fsig(accG[nt][0] + bg0) * ma;
        oa.y = (accP[nt][1] + bp1) * fsig(accG[nt][1] + bg1) * ma;
        ob.x = (accP[nt][2] + bp0) * fsig(accG[nt][2] + bg0) * mb;
        ob.y = (accP[nt][3] + bp1) * fsig(accG[nt][3] + bg1) * mb;
        *reinterpret_cast<float2*>(&dst[(size_t)ra * DCH + col]) = oa;
        *reinterpret_cast<float2*>(&dst[(size_t)rb * DCH + col]) = ob;
    }
}

// single: EPI 1: g_gate = sigmoid(X@W + b);  EPI 0: dstExt = PRE@W + b
template<int WIDX, int EPI>
__global__ __launch_bounds__(256, 2) void proj_single_mma(
    const float* __restrict__ bias, float* __restrict__ dstExt)
{
    extern __shared__ char smem[];
    const uint32_t sbase = (uint32_t)__cvta_generic_to_shared(smem);
    const int t = threadIdx.x, lane = t & 31, wid = t >> 5;
    const int wm = wid & 3, wn = wid >> 2;
    const int row0 = blockIdx.x * 64;
    const __nv_bfloat16* __restrict__ ah = (EPI == 1) ? g_Xh : g_Lh;
    const __nv_bfloat16* __restrict__ al = (EPI == 1) ? g_Xl : g_Ll;
    float* __restrict__ dst = (EPI == 1) ? g_gate : dstExt;

    const __nv_bfloat16* __restrict__ wh = g_Wth + WIDX * (DCH*DCH);
    const __nv_bfloat16* __restrict__ wl = g_Wtl + WIDX * (DCH*DCH);

    float acc[8][4];
#pragma unroll
    for (int nt = 0; nt < 8; nt++)
#pragma unroll
        for (int c = 0; c < 4; c++) acc[nt][c] = 0.f;

    auto fill = [&](int s) {
        char* base = smem + (s & 1) * PJ_STAGE_S;
#pragma unroll
        for (int q = 0; q < 2; q++) {
            int c = t + q * 256;
            int hl = c >> 8, row = (c >> 2) & 63, col = c & 3;
            const __nv_bfloat16* src = hl ? al : ah;
            cp16(base + hl * PJ_A_T + row * PJ_RS + col * 16,
                 src + (size_t)(row0 + row) * DCH + s * 32 + col * 8);
        }
        const __nv_bfloat16* wsrc[2] = {wh, wl};
#pragma unroll
        for (int q = 0; q < 4; q++) {
            int c = t + q * 256;
            int m = c >> 9, n = (c >> 2) & 127, col = c & 3;
            cp16(base + 2 * PJ_A_T + m * PJ_B_T + n * PJ_RS + col * 16,
                 wsrc[m] + n * DCH + s * 32 + col * 8);
        }
    };

    fill(0); asm volatile("cp.async.commit_group;");
    fill(1); asm volatile("cp.async.commit_group;");

    const uint32_t aOff = (uint32_t)((wm * 16 + (lane & 15)) * PJ_RS + ((lane >> 4) << 4));
    const uint32_t bOff = (uint32_t)((wn * 64 + (lane & 15)) * PJ_RS + ((lane >> 4) << 4));

    for (int s = 0; s < 4; s++) {
        asm volatile("cp.async.wait_group 1;");
        __syncthreads();
        const uint32_t sb = sbase + (s & 1) * PJ_STAGE_S;
#pragma unroll
        for (int kh = 0; kh < 2; kh++) {
            uint32_t aH[4], aL[4];
            ldsm_x4(aH, sb + aOff + kh * 32);
            ldsm_x4(aL, sb + PJ_A_T + aOff + kh * 32);
#pragma unroll
            for (int ntp = 0; ntp < 4; ntp++) {
                const uint32_t bo = bOff + ntp * 16 * PJ_RS + kh * 32;
                uint32_t bH[4], bL[4];
                ldsm_x4(bH, sb + 2*PJ_A_T + bo);
                ldsm_x4(bL, sb + 2*PJ_A_T + PJ_B_T + bo);
                mma3(acc[2*ntp  ], aH, aL, bH[0], bH[2], bL[0], bL[2]);
                mma3(acc[2*ntp+1], aH, aL, bH[1], bH[3], bL[1], bL[3]);
            }
        }
        __syncthreads();
        if (s + 2 < 4) fill(s + 2);
        asm volatile("cp.async.commit_group;");
    }

    const int g  = lane >> 2;
    const int kc = (lane & 3) * 2;
    const int ra = row0 + wm * 16 + g, rb = ra + 8;
#pragma unroll
    for (int nt = 0; nt < 8; nt++) {
        const int col = wn * 64 + nt * 8 + kc;
        const float b0 = bias[col], b1 = bias[col + 1];
        float2 oa, ob;
        oa.x = acc[nt][0] + b0; oa.y = acc[nt][1] + b1;
        ob.x = acc[nt][2] + b0; ob.y = acc[nt][3] + b1;
        if (EPI == 1) { oa.x = fsig(oa.x); oa.y = fsig(oa.y);
                        ob.x = fsig(ob.x); ob.y = fsig(ob.y); }
        *reinterpret_cast<float2*>(&dst[(size_t)ra * DCH + col]) = oa;
        *reinterpret_cast<float2*>(&dst[(size_t)rb * DCH + col]) = ob;
    }
}

// ---------------------------------------------------------------------------
// T1: split left[pos][d] -> Lh/Ll[d][pos] bf16 (R8, proven).
// ---------------------------------------------------------------------------
__global__ __launch_bounds__(256) void splitL_kernel()
{
    __shared__ float sX[32][128];
    const int t = threadIdx.x;
    const size_t pos0 = (size_t)blockIdx.x * 32;
#pragma unroll
    for (int q = 0; q < 4; q++) {
        int idx = t + q * 256;
        int row = idx >> 5, c4 = idx & 31;
        float4 v = reinterpret_cast<const float4*>(g_left)[(pos0 + row) * 32 + c4];
        *reinterpret_cast<float4*>(&sX[row][c4 * 4]) = v;
    }
    __syncthreads();
    const int d = t >> 1, h = (t & 1) * 16;
    uint32_t wh[8], wl[8];
#pragma unroll
    for (int q = 0; q < 8; q++) {
        __nv_bfloat16 h0, l0, h1, l1;
        bsplit(sX[h + 2*q    ][d], h0, l0);
        bsplit(sX[h + 2*q + 1][d], h1, l1);
        wh[q] = pack2(h0, h1);
        wl[q] = pack2(l0, l1);
    }
    const size_t ob = (size_t)d * NPOS + pos0 + h;
    *reinterpret_cast<uint4*>(&g_Lh[ob])     = make_uint4(wh[0], wh[1], wh[2], wh[3]);
    *reinterpret_cast<uint4*>(&g_Lh[ob + 8]) = make_uint4(wh[4], wh[5], wh[6], wh[7]);
    *reinterpret_cast<uint4*>(&g_Ll[ob])     = make_uint4(wl[0], wl[1], wl[2], wl[3]);
    *reinterpret_cast<uint4*>(&g_Ll[ob + 8]) = make_uint4(wl[4], wl[5], wl[6], wl[7]);
}

// ---------------------------------------------------------------------------
// T2: split+transpose right[(j,k)][d] -> Rh/Rl[d][k][j] bf16 (R8, proven).
// ---------------------------------------------------------------------------
__global__ __launch_bounds__(256) void splitR_kernel()
{
    __shared__ float sY[32 * 8 * 33];
    const int t = threadIdx.x;
    const int b = blockIdx.x;
    const int dg = b >> 8;
    const int kb = (b >> 4) & 15;
    const int jb = b & 15;
    const int j0 = jb * 32, k0 = kb * 32, d0 = dg * 8;
#pragma unroll
    for (int q = 0; q < 8; q++) {
        int idx = t + q * 256;
        int j   = idx >> 6;
        int rem = idx & 63;
        int k   = rem >> 1;
        int dq  = rem & 1;
        float4 v = reinterpret_cast<const float4*>(g_right)[
            ((size_t)(j0 + j) * NRES + k0 + k) * 32 + (d0 >> 2) + dq];
        float* dstp = &sY[(k * 8 + dq * 4) * 33 + j];
        dstp[0]  = v.x; dstp[33] = v.y; dstp[66] = v.z; dstp[99] = v.w;
    }
    __syncthreads();
    const int d = t >> 5, k = t & 31;
    const float* src = &sY[(k * 8 + d) * 33];
    uint32_t wh[16], wl[16];
#pragma unroll
    for (int q = 0; q < 16; q++) {
        __nv_bfloat16 h0, l0, h1, l1;
        bsplit(src[2*q    ], h0, l0);
        bsplit(src[2*q + 1], h1, l1);
        wh[q] = pack2(h0, h1);
        wl[q] = pack2(l0, l1);
    }
    const size_t ob = ((size_t)(d0 + d) * NRES + k0 + k) * NRES + j0;
#pragma unroll
    for (int q = 0; q < 4; q++) {
        *reinterpret_cast<uint4*>(&g_Rh[ob + q * 8]) =
            make_uint4(wh[q*4], wh[q*4+1], wh[q*4+2], wh[q*4+3]);
        *reinterpret_cast<uint4*>(&g_Rl[ob + q * 8]) =
            make_uint4(wl[q*4], wl[q*4+1], wl[q*4+2], wl[q*4+3]);
    }
}

// ---------------------------------------------------------------------------
// K4: einsum via mma.sync (R8, proven — unchanged).
// ---------------------------------------------------------------------------
#define EM_RS     80
#define EM_A_T    (128 * EM_RS)
#define EM_B_T    (64 * EM_RS)
#define EM_STAGE  (2 * EM_A_T + 2 * EM_B_T)
#define EM_SMEM   (3 * EM_STAGE)

__global__ __launch_bounds__(256, 2) void einsum_mma_kernel()
{
    extern __shared__ char smem[];
    const uint32_t sbase = (uint32_t)__cvta_generic_to_shared(smem);
    const int t    = threadIdx.x;
    const int lane = t & 31;
    const int wid  = t >> 5;
    const int wm   = wid & 3;
    const int wn   = wid >> 2;

    const int bid = blockIdx.x;
    const int d   = bid >> 5;
    const int i0  = ((bid >> 3) & 3) * 128;
    const int k0  = (bid & 7) * 64;

    const __nv_bfloat16* __restrict__ pLh = g_Lh + (size_t)d * NPOS + (size_t)i0 * NRES;
    const __nv_bfloat16* __restrict__ pLl = g_Ll + (size_t)d * NPOS + (size_t)i0 * NRES;
    const __nv_bfloat16* __restrict__ pRh = g_Rh + (size_t)d * NPOS + (size_t)k0 * NRES;
    const __nv_bfloat16* __restrict__ pRl = g_Rl + (size_t)d * NPOS + (size_t)k0 * NRES;

    float acc[2][4][4];
#pragma unroll
    for (int mt = 0; mt < 2; mt++)
#pragma unroll
        for (int nt = 0; nt < 4; nt++)
#pragma unroll
            for (int c = 0; c < 4; c++) acc[mt][nt][c] = 0.0f;

    auto fill = [&](int s) {
        const int buf = s % 3;
        char* base = smem + buf * EM_STAGE;
        const int j0s = s * 32;
        {
            int c0 = t, c1 = t + 256;
            int r0 = c0 >> 2, r1 = c1 >> 2, col0 = c0 & 3, col1 = c1 & 3;
            cp16(base + r0 * EM_RS + col0 * 16,
                 pLh + (size_t)r0 * NRES + j0s + col0 * 8);
            cp16(base + r1 * EM_RS + col1 * 16,
                 pLh + (size_t)r1 * NRES + j0s + col1 * 8);
            cp16(base + EM_A_T + r0 * EM_RS + col0 * 16,
                 pLl + (size_t)r0 * NRES + j0s + col0 * 8);
            cp16(base + EM_A_T + r1 * EM_RS + col1 * 16,
                 pLl + (size_t)r1 * NRES + j0s + col1 * 8);
        }
        {
            int r = t >> 2, col = t & 3;
            cp16(base + 2 * EM_A_T + r * EM_RS + col * 16,
                 pRh + (size_t)r * NRES + j0s + col * 8);
            cp16(base + 2 * EM_A_T + EM_B_T + r * EM_RS + col * 16,
                 pRl + (size_t)r * NRES + j0s + col * 8);
        }
    };

    fill(0); asm volatile("cp.async.commit_group;");
    fill(1); asm volatile("cp.async.commit_group;");

    const uint32_t aOff = (uint32_t)((wm * 32 + ((lane >> 3) & 1) * 8 + (lane & 7)) * EM_RS
                                     + ((lane >> 4) << 4));
    const uint32_t bOff = (uint32_t)((wn * 32 + (lane & 7)) * EM_RS
                                     + (((lane >> 3) & 1) << 4));

    for (int s = 0; s < 16; s++) {
        asm volatile("cp.async.wait_group 1;");
        __syncthreads();
        if (s + 2 < 16) fill(s + 2);
        asm volatile("cp.async.commit_group;");

        const uint32_t sb  = sbase + (s % 3) * EM_STAGE;
        const uint32_t aHb = sb, aLb = sb + EM_A_T;
        const uint32_t bHb = sb + 2 * EM_A_T, bLb = bHb + EM_B_T;

#pragma unroll
        for (int kh = 0; kh < 2; kh++) {
            const uint32_t kb = kh * 32;
            uint32_t aH[2][4], aL[2][4];
            ldsm_x4(aH[0], aHb + aOff + kb);
            ldsm_x4(aH[1], aHb + aOff + 16 * EM_RS + kb);
            ldsm_x4(aL[0], aLb + aOff + kb);
            ldsm_x4(aL[1], aLb + aOff + 16 * EM_RS + kb);
#pragma unroll
            for (int nt = 0; nt < 4; nt++) {
                uint32_t bH[2], bL[2];
                ldsm_x2(bH, bHb + bOff + nt * 8 * EM_RS + kb);
                ldsm_x2(bL, bLb + bOff + nt * 8 * EM_RS + kb);
#pragma unroll
                for (int mt = 0; mt < 2; mt++) {
                    mma16816(acc[mt][nt], aH[mt], bH);
                    mma16816(acc[mt][nt], aH[mt], bL);
                    mma16816(acc[mt][nt], aL[mt], bH);
                }
            }
        }
    }

    float* __restrict__ pOut = g_pret + (size_t)d * NPOS;
    const int g  = lane >> 2;
    const int kc = (lane & 3) * 2;
#pragma unroll
    for (int mt = 0; mt < 2; mt++) {
#pragma unroll
        for (int nt = 0; nt < 4; nt++) {
            const int i = i0 + wm * 32 + mt * 16 + g;
            const int k = k0 + wn * 32 + nt * 8 + kc;
            *reinterpret_cast<float2*>(&pOut[(size_t)i * NRES + k]) =
                make_float2(acc[mt][nt][0], acc[mt][nt][1]);
            *reinterpret_cast<float2*>(&pOut[(size_t)(i + 8) * NRES + k]) =
                make_float2(acc[mt][nt][2], acc[mt][nt][3]);
        }
    }
}

// ---------------------------------------------------------------------------
// T3: pre = pret^T * gate -> split into Ph/Pl bf16 [pos][d] (reuses g_Lh/g_Ll)
// ---------------------------------------------------------------------------
__global__ __launch_bounds__(256) void fuse_gate_kernel()
{
    __shared__ float sP[32][128];
    const int t = threadIdx.x;
    const size_t pos0 = (size_t)blockIdx.x * 32;
    const int d = t >> 1, h = (t & 1) * 16;
#pragma unroll
    for (int q = 0; q < 4; q++) {
        float4 v = reinterpret_cast<const float4*>(g_pret)[
            ((size_t)d * NPOS + pos0 + h) / 4 + q];
        sP[h + q*4 + 0][d] = v.x;
        sP[h + q*4 + 1][d] = v.y;
        sP[h + q*4 + 2][d] = v.z;
        sP[h + q*4 + 3][d] = v.w;
    }
    __syncthreads();
#pragma unroll
    for (int q = 0; q < 4; q++) {
        int idx = t + q * 256;
        int row = idx >> 5, c4 = idx & 31;
        float4 p = *reinterpret_cast<float4*>(&sP[row][c4 * 4]);
        float4 g = reinterpret_cast<const float4*>(g_gate)[(pos0 + row) * 32 + c4];
        p.x *= g.x; p.y *= g.y; p.z *= g.z; p.w *= g.w;
        __nv_bfloat16 h0,l0,h1,l1,h2,l2,h3,l3;
        bsplit(p.x,h0,l0); bsplit(p.y,h1,l1); bsplit(p.z,h2,l2); bsplit(p.w,h3,l3);
        const size_t o = (pos0 + row) * DCH + c4 * 4;
        *reinterpret_cast<uint2*>(&g_Lh[o]) = make_uint2(pack2(h0,h1), pack2(h2,h3));
        *reinterpret_cast<uint2*>(&g_Ll[o]) = make_uint2(pack2(l0,l1), pack2(l2,l3));
    }
}

// ---------------------------------------------------------------------------
extern "C" void kernel_launch(void* const* d_in, const int* in_sizes, int n_in,
                              void* d_out, int out_size)
{
    (void)in_sizes; (void)n_in; (void)out_size;
    const float* pair = (const float*)d_in[0];
    const float* mask = (const float*)d_in[1];
    const float* ln_g = (const float*)d_in[2];
    const float* ln_b = (const float*)d_in[3];
    const float* w_lp = (const float*)d_in[4];
    const float* b_lp = (const float*)d_in[5];
    const float* w_lg = (const float*)d_in[6];
    const float* b_lg = (const float*)d_in[7];
    const float* w_rp = (const float*)d_in[8];
    const float* b_rp = (const float*)d_in[9];
    const float* w_rg = (const float*)d_in[10];
    const float* b_rg = (const float*)d_in[11];
    const float* w_g  = (const float*)d_in[12];
    const float* b_g  = (const float*)d_in[13];
    const float* w_o  = (const float*)d_in[14];
    const float* b_o  = (const float*)d_in[15];
    float* out = (float*)d_out;

    cudaFuncSetAttribute(einsum_mma_kernel,
                         cudaFuncAttributeMaxDynamicSharedMemorySize, EM_SMEM);
    cudaFuncSetAttribute(proj_dual_mma<0,1,0>,
                         cudaFuncAttributeMaxDynamicSharedMemorySize, PJ_SMEM_D);
    cudaFuncSetAttribute(proj_dual_mma<2,3,1>,
                         cudaFuncAttributeMaxDynamicSharedMemorySize, PJ_SMEM_D);
    cudaFuncSetAttribute(proj_single_mma<4,1>,
                         cudaFuncAttributeMaxDynamicSharedMemorySize, PJ_SMEM_S);
    cudaFuncSetAttribute(proj_single_mma<5,0>,
                         cudaFuncAttributeMaxDynamicSharedMemorySize, PJ_SMEM_S);

    prep_weights<<<6, 256>>>(w_lp, w_lg, w_rp, w_rg, w_g, w_o);
    ln_split_kernel<<<NPOS / 8, 256>>>(pair, ln_g, ln_b);
    proj_dual_mma<0,1,0><<<NPOS / 64, 256, PJ_SMEM_D>>>(b_lp, b_lg, mask);
    proj_dual_mma<2,3,1><<<NPOS / 64, 256, PJ_SMEM_D>>>(b_rp, b_rg, mask);
    proj_single_mma<4,1><<<NPOS / 64, 256, PJ_SMEM_S>>>(b_g, nullptr);
    splitL_kernel<<<NPOS / 32, 256>>>();
    splitR_kernel<<<4096, 256>>>();
    einsum_mma_kernel<<<4096, 256, EM_SMEM>>>();
    fuse_gate_kernel<<<NPOS / 32, 256>>>();
    proj_single_mma<5,0><<<NPOS / 64, 256, PJ_SMEM_S>>>(b_o, out);
}

// round 10
// speedup vs baseline: 3.4870x; 1.1087x over previous
#include <cuda_runtime.h>
#include <cuda_bf16.h>
#include <cstdint>

#define NRES 512
#define DCH  128
#define NPOS (NRES*NRES)

// Scratch (device globals — no runtime allocation allowed)
__device__ float g_gate [(size_t)NPOS * DCH];
__device__ float g_pret [(size_t)NPOS * DCH];        // [d][i][k]
__device__ __nv_bfloat16 g_Xh[(size_t)NPOS * DCH];   // LN(x) split, [pos][d]
__device__ __nv_bfloat16 g_Xl[(size_t)NPOS * DCH];
__device__ __nv_bfloat16 g_Lh[(size_t)DCH * NPOS];   // [d][i][j]; later pre-split [pos][d]
__device__ __nv_bfloat16 g_Ll[(size_t)DCH * NPOS];
__device__ __nv_bfloat16 g_Rh[(size_t)DCH * NPOS];   // [d][k][j]
__device__ __nv_bfloat16 g_Rl[(size_t)DCH * NPOS];
__device__ __nv_bfloat16 g_Wth[6 * DCH * DCH];       // W^T hi, [widx][n][k]
__device__ __nv_bfloat16 g_Wtl[6 * DCH * DCH];       // W^T lo

__device__ __forceinline__ float fsig(float x) { return 1.0f / (1.0f + __expf(-x)); }

__device__ __forceinline__ void cp16(void* s, const void* g) {
    unsigned sa = (unsigned)__cvta_generic_to_shared(s);
    asm volatile("cp.async.cg.shared.global [%0], [%1], 16;" :: "r"(sa), "l"(g));
}

// ---- mma.sync / ldmatrix (sm_80-class PTX: compiles on plain sm_103) ------
__device__ __forceinline__ void ldsm_x4(uint32_t* r, uint32_t addr) {
    asm volatile("ldmatrix.sync.aligned.m8n8.x4.shared.b16 {%0,%1,%2,%3}, [%4];"
        : "=r"(r[0]), "=r"(r[1]), "=r"(r[2]), "=r"(r[3]) : "r"(addr));
}
__device__ __forceinline__ void ldsm_x2(uint32_t* r, uint32_t addr) {
    asm volatile("ldmatrix.sync.aligned.m8n8.x2.shared.b16 {%0,%1}, [%2];"
        : "=r"(r[0]), "=r"(r[1]) : "r"(addr));
}
__device__ __forceinline__ void mma16816(float* c, const uint32_t* a, const uint32_t* b) {
    asm volatile("mma.sync.aligned.m16n8k16.row.col.f32.bf16.bf16.f32 "
        "{%0,%1,%2,%3}, {%4,%5,%6,%7}, {%8,%9}, {%0,%1,%2,%3};"
        : "+f"(c[0]), "+f"(c[1]), "+f"(c[2]), "+f"(c[3])
        : "r"(a[0]), "r"(a[1]), "r"(a[2]), "r"(a[3]), "r"(b[0]), "r"(b[1]));
}
// C += Ah*Bh + Ah*Bl + Al*Bh   (bf16 hi/lo split product)
__device__ __forceinline__ void mma3(float* c, const uint32_t* aH, const uint32_t* aL,
                                     uint32_t bh0, uint32_t bh1,
                                     uint32_t bl0, uint32_t bl1) {
    uint32_t b[2];
    b[0] = bh0; b[1] = bh1; mma16816(c, aH, b);
    b[0] = bl0; b[1] = bl1; mma16816(c, aH, b);
    b[0] = bh0; b[1] = bh1; mma16816(c, aL, b);
}

__device__ __forceinline__ void bsplit(float v, __nv_bfloat16& h, __nv_bfloat16& l) {
    h = __float2bfloat16(v);
    l = __float2bfloat16(v - __bfloat162float(h));
}
__device__ __forceinline__ uint32_t pack2(__nv_bfloat16 a, __nv_bfloat16 b) {
    __nv_bfloat162 p(a, b);
    return *reinterpret_cast<uint32_t*>(&p);
}

// ---------------------------------------------------------------------------
// K0: weight prep — W[k][n] -> Wt_h/Wt_l[n][k] bf16. One block per matrix.
// ---------------------------------------------------------------------------
__global__ void prep_weights(const float* w0, const float* w1, const float* w2,
                             const float* w3, const float* w4, const float* w5)
{
    const float* srcs[6] = {w0, w1, w2, w3, w4, w5};
    const float* src = srcs[blockIdx.x];
    const int base = blockIdx.x * DCH * DCH;
    for (int idx = threadIdx.x; idx < DCH * DCH; idx += blockDim.x) {
        int k = idx >> 7, n = idx & 127;
        __nv_bfloat16 h, l;
        bsplit(src[idx], h, l);
        g_Wth[base + n * DCH + k] = h;
        g_Wtl[base + n * DCH + k] = l;
    }
}

// ---------------------------------------------------------------------------
// K1: LayerNorm over D=128 -> Xh/Xl bf16 [pos][d].
// ---------------------------------------------------------------------------
__global__ void ln_split_kernel(const float* __restrict__ pair,
                                const float* __restrict__ lng,
                                const float* __restrict__ lnb)
{
    const int lane = threadIdx.x & 31;
    const int row  = blockIdx.x * 8 + (threadIdx.x >> 5);
    const float4 v = reinterpret_cast<const float4*>(pair)[(size_t)row * 32 + lane];
    float s = v.x + v.y + v.z + v.w;
    float q = v.x*v.x + v.y*v.y + v.z*v.z + v.w*v.w;
#pragma unroll
    for (int o = 16; o > 0; o >>= 1) {
        s += __shfl_xor_sync(0xffffffffu, s, o);
        q += __shfl_xor_sync(0xffffffffu, q, o);
    }
    const float mean = s * (1.0f / 128.0f);
    const float var  = q * (1.0f / 128.0f) - mean * mean;
    const float rs   = rsqrtf(var + 1e-5f);
    const float4 g4 = reinterpret_cast<const float4*>(lng)[lane];
    const float4 b4 = reinterpret_cast<const float4*>(lnb)[lane];
    float o0 = (v.x - mean) * rs * g4.x + b4.x;
    float o1 = (v.y - mean) * rs * g4.y + b4.y;
    float o2 = (v.z - mean) * rs * g4.z + b4.z;
    float o3 = (v.w - mean) * rs * g4.w + b4.w;
    __nv_bfloat16 h0,l0,h1,l1,h2,l2,h3,l3;
    bsplit(o0,h0,l0); bsplit(o1,h1,l1); bsplit(o2,h2,l2); bsplit(o3,h3,l3);
    uint2 hv = make_uint2(pack2(h0,h1), pack2(h2,h3));
    uint2 lv = make_uint2(pack2(l0,l1), pack2(l2,l3));
    *reinterpret_cast<uint2*>(&g_Xh[(size_t)row * DCH + lane * 4]) = hv;
    *reinterpret_cast<uint2*>(&g_Xl[(size_t)row * DCH + lane * 4]) = lv;
}

// ---------------------------------------------------------------------------
// Projection GEMMs on mma.sync. M tile 64 x N 128, K=128 in 4 stages of 32.
// 8 warps = 4M x 2N, warp = 16 rows x 64 cols.
// ---------------------------------------------------------------------------
#define PJ_RS      80
#define PJ_A_T     (64 * PJ_RS)               // 5120
#define PJ_B_T     (128 * PJ_RS)              // 10240
#define PJ_STAGE_D (2*PJ_A_T + 4*PJ_B_T)      // 51200
#define PJ_SMEM_D  (2 * PJ_STAGE_D)           // 102400
#define PJ_STAGE_S (2*PJ_A_T + 2*PJ_B_T)      // 30720
#define PJ_SMEM_S  (2 * PJ_STAGE_S)           // 61440

// dual: v = (X@Wp + bp) * sigmoid(X@Wg + bg) * mask, then hi/lo split + transpose
// DST 0 -> g_Lh/g_Ll [d][i][j] (rows = 64 consecutive pos, fixed i)
// DST 1 -> g_Rh/g_Rl [d][k][j] (rows = pos (j0+r)*512+k, fixed k)
template<int WP, int WG, int DST>
__global__ __launch_bounds__(256, 2) void proj_dual_mma(
    const float* __restrict__ bp, const float* __restrict__ bg,
    const float* __restrict__ mask)
{
    extern __shared__ char smem[];
    const uint32_t sbase = (uint32_t)__cvta_generic_to_shared(smem);
    const int t = threadIdx.x, lane = t & 31, wid = t >> 5;
    const int wm = wid & 3, wn = wid >> 2;

    // row mapping
    const int row0 = blockIdx.x * 64;          // DST==0
    const int kk   = blockIdx.x >> 3;          // DST==1
    const int j0   = (blockIdx.x & 7) * 64;    // DST==1

    auto apos = [&](int row) -> size_t {
        if (DST == 0) return (size_t)(row0 + row);
        else          return (size_t)(j0 + row) * NRES + kk;
    };

    const __nv_bfloat16* __restrict__ wph = g_Wth + WP * (DCH*DCH);
    const __nv_bfloat16* __restrict__ wpl = g_Wtl + WP * (DCH*DCH);
    const __nv_bfloat16* __restrict__ wgh = g_Wth + WG * (DCH*DCH);
    const __nv_bfloat16* __restrict__ wgl = g_Wtl + WG * (DCH*DCH);

    float accP[8][4], accG[8][4];
#pragma unroll
    for (int nt = 0; nt < 8; nt++)
#pragma unroll
        for (int c = 0; c < 4; c++) { accP[nt][c] = 0.f; accG[nt][c] = 0.f; }

    auto fill = [&](int s) {
        char* base = smem + (s & 1) * PJ_STAGE_D;
#pragma unroll
        for (int q = 0; q < 2; q++) {           // A: Xh, Xl
            int c = t + q * 256;
            int hl = c >> 8, row = (c >> 2) & 63, col = c & 3;
            const __nv_bfloat16* src = hl ? g_Xl : g_Xh;
            cp16(base + hl * PJ_A_T + row * PJ_RS + col * 16,
                 src + apos(row) * DCH + s * 32 + col * 8);
        }
        const __nv_bfloat16* wsrc[4] = {wph, wpl, wgh, wgl};
#pragma unroll
        for (int q = 0; q < 8; q++) {           // B: ph, pl, gh, gl
            int c = t + q * 256;
            int m = c >> 9, n = (c >> 2) & 127, col = c & 3;
            cp16(base + 2 * PJ_A_T + m * PJ_B_T + n * PJ_RS + col * 16,
                 wsrc[m] + n * DCH + s * 32 + col * 8);
        }
    };

    fill(0); asm volatile("cp.async.commit_group;");
    fill(1); asm volatile("cp.async.commit_group;");

    const uint32_t aOff = (uint32_t)((wm * 16 + (lane & 15)) * PJ_RS + ((lane >> 4) << 4));
    const uint32_t bOff = (uint32_t)((wn * 64 + (lane & 15)) * PJ_RS + ((lane >> 4) << 4));

    for (int s = 0; s < 4; s++) {
        asm volatile("cp.async.wait_group 1;");
        __syncthreads();
        const uint32_t sb = sbase + (s & 1) * PJ_STAGE_D;
#pragma unroll
        for (int kh = 0; kh < 2; kh++) {
            uint32_t aH[4], aL[4];
            ldsm_x4(aH, sb + aOff + kh * 32);
            ldsm_x4(aL, sb + PJ_A_T + aOff + kh * 32);
#pragma unroll
            for (int ntp = 0; ntp < 4; ntp++) {
                const uint32_t bo = bOff + ntp * 16 * PJ_RS + kh * 32;
                uint32_t pH[4], pL[4], gH[4], gL[4];
                ldsm_x4(pH, sb + 2*PJ_A_T + bo);
                ldsm_x4(pL, sb + 2*PJ_A_T + PJ_B_T + bo);
                ldsm_x4(gH, sb + 2*PJ_A_T + 2*PJ_B_T + bo);
                ldsm_x4(gL, sb + 2*PJ_A_T + 3*PJ_B_T + bo);
                mma3(accP[2*ntp  ], aH, aL, pH[0], pH[2], pL[0], pL[2]);
                mma3(accP[2*ntp+1], aH, aL, pH[1], pH[3], pL[1], pL[3]);
                mma3(accG[2*ntp  ], aH, aL, gH[0], gH[2], gL[0], gL[2]);
                mma3(accG[2*ntp+1], aH, aL, gH[1], gH[3], gL[1], gL[3]);
            }
        }
        __syncthreads();                 // all warps done reading buffer s&1
        if (s + 2 < 4) fill(s + 2);
        asm volatile("cp.async.commit_group;");
    }

    // ---- Epilogue: gated value -> smem fp32 [64][129] -> bf16 hi/lo, d-major
    float* sP = reinterpret_cast<float*>(smem);   // 64*129*4 = 33024 B, fits
    const int g  = lane >> 2;
    const int kc = (lane & 3) * 2;
    const int ra = wm * 16 + g, rb = ra + 8;      // tile-local rows
    const float ma = mask[apos(ra)];
    const float mb = mask[apos(rb)];
#pragma unroll
    for (int nt = 0; nt < 8; nt++) {
        const int col = wn * 64 + nt * 8 + kc;
        const float bp0 = bp[col], bp1 = bp[col + 1];
        const float bg0 = bg[col], bg1 = bg[col + 1];
        sP[ra * 129 + col    ] = (accP[nt][0] + bp0) * fsig(accG[nt][0] + bg0) * ma;
        sP[ra * 129 + col + 1] = (accP[nt][1] + bp1) * fsig(accG[nt][1] + bg1) * ma;
        sP[rb * 129 + col    ] = (accP[nt][2] + bp0) * fsig(accG[nt][2] + bg0) * mb;
        sP[rb * 129 + col + 1] = (accP[nt][3] + bp1) * fsig(accG[nt][3] + bg1) * mb;
    }
    __syncthreads();
    // thread t: channel dch = t>>1, rows h..h+31 (h = 0 or 32)
    const int dch = t >> 1, h = (t & 1) * 32;
    uint32_t wh[16], wl[16];
#pragma unroll
    for (int q = 0; q < 16; q++) {
        __nv_bfloat16 h0, l0, h1, l1;
        bsplit(sP[(h + 2*q    ) * 129 + dch], h0, l0);
        bsplit(sP[(h + 2*q + 1) * 129 + dch], h1, l1);
        wh[q] = pack2(h0, h1);
        wl[q] = pack2(l0, l1);
    }
    size_t ob;
    if (DST == 0) ob = (size_t)dch * NPOS + row0 + h;                     // [d][pos]
    else          ob = (size_t)dch * NPOS + (size_t)kk * NRES + j0 + h;   // [d][k][j]
    __nv_bfloat16* __restrict__ dH = DST ? g_Rh : g_Lh;
    __nv_bfloat16* __restrict__ dL = DST ? g_Rl : g_Ll;
#pragma unroll
    for (int q = 0; q < 4; q++) {
        *reinterpret_cast<uint4*>(&dH[ob + q * 8]) =
            make_uint4(wh[q*4], wh[q*4+1], wh[q*4+2], wh[q*4+3]);
        *reinterpret_cast<uint4*>(&dL[ob + q * 8]) =
            make_uint4(wl[q*4], wl[q*4+1], wl[q*4+2], wl[q*4+3]);
    }
}

// single: EPI 1: g_gate = sigmoid(X@W + b);  EPI 0: dstExt = PRE@W + b
template<int WIDX, int EPI>
__global__ __launch_bounds__(256, 2) void proj_single_mma(
    const float* __restrict__ bias, float* __restrict__ dstExt)
{
    extern __shared__ char smem[];
    const uint32_t sbase = (uint32_t)__cvta_generic_to_shared(smem);
    const int t = threadIdx.x, lane = t & 31, wid = t >> 5;
    const int wm = wid & 3, wn = wid >> 2;
    const int row0 = blockIdx.x * 64;
    const __nv_bfloat16* __restrict__ ah = (EPI == 1) ? g_Xh : g_Lh;
    const __nv_bfloat16* __restrict__ al = (EPI == 1) ? g_Xl : g_Ll;
    float* __restrict__ dst = (EPI == 1) ? g_gate : dstExt;

    const __nv_bfloat16* __restrict__ wh = g_Wth + WIDX * (DCH*DCH);
    const __nv_bfloat16* __restrict__ wl = g_Wtl + WIDX * (DCH*DCH);

    float acc[8][4];
#pragma unroll
    for (int nt = 0; nt < 8; nt++)
#pragma unroll
        for (int c = 0; c < 4; c++) acc[nt][c] = 0.f;

    auto fill = [&](int s) {
        char* base = smem + (s & 1) * PJ_STAGE_S;
#pragma unroll
        for (int q = 0; q < 2; q++) {
            int c = t + q * 256;
            int hl = c >> 8, row = (c >> 2) & 63, col = c & 3;
            const __nv_bfloat16* src = hl ? al : ah;
            cp16(base + hl * PJ_A_T + row * PJ_RS + col * 16,
                 src + (size_t)(row0 + row) * DCH + s * 32 + col * 8);
        }
        const __nv_bfloat16* wsrc[2] = {wh, wl};
#pragma unroll
        for (int q = 0; q < 4; q++) {
            int c = t + q * 256;
            int m = c >> 9, n = (c >> 2) & 127, col = c & 3;
            cp16(base + 2 * PJ_A_T + m * PJ_B_T + n * PJ_RS + col * 16,
                 wsrc[m] + n * DCH + s * 32 + col * 8);
        }
    };

    fill(0); asm volatile("cp.async.commit_group;");
    fill(1); asm volatile("cp.async.commit_group;");

    const uint32_t aOff = (uint32_t)((wm * 16 + (lane & 15)) * PJ_RS + ((lane >> 4) << 4));
    const uint32_t bOff = (uint32_t)((wn * 64 + (lane & 15)) * PJ_RS + ((lane >> 4) << 4));

    for (int s = 0; s < 4; s++) {
        asm volatile("cp.async.wait_group 1;");
        __syncthreads();
        const uint32_t sb = sbase + (s & 1) * PJ_STAGE_S;
#pragma unroll
        for (int kh = 0; kh < 2; kh++) {
            uint32_t aH[4], aL[4];
            ldsm_x4(aH, sb + aOff + kh * 32);
            ldsm_x4(aL, sb + PJ_A_T + aOff + kh * 32);
#pragma unroll
            for (int ntp = 0; ntp < 4; ntp++) {
                const uint32_t bo = bOff + ntp * 16 * PJ_RS + kh * 32;
                uint32_t bH[4], bL[4];
                ldsm_x4(bH, sb + 2*PJ_A_T + bo);
                ldsm_x4(bL, sb + 2*PJ_A_T + PJ_B_T + bo);
                mma3(acc[2*ntp  ], aH, aL, bH[0], bH[2], bL[0], bL[2]);
                mma3(acc[2*ntp+1], aH, aL, bH[1], bH[3], bL[1], bL[3]);
            }
        }
        __syncthreads();
        if (s + 2 < 4) fill(s + 2);
        asm volatile("cp.async.commit_group;");
    }

    const int g  = lane >> 2;
    const int kc = (lane & 3) * 2;
    const int ra = row0 + wm * 16 + g, rb = ra + 8;
#pragma unroll
    for (int nt = 0; nt < 8; nt++) {
        const int col = wn * 64 + nt * 8 + kc;
        const float b0 = bias[col], b1 = bias[col + 1];
        float2 oa, ob;
        oa.x = acc[nt][0] + b0; oa.y = acc[nt][1] + b1;
        ob.x = acc[nt][2] + b0; ob.y = acc[nt][3] + b1;
        if (EPI == 1) { oa.x = fsig(oa.x); oa.y = fsig(oa.y);
                        ob.x = fsig(ob.x); ob.y = fsig(ob.y); }
        *reinterpret_cast<float2*>(&dst[(size_t)ra * DCH + col]) = oa;
        *reinterpret_cast<float2*>(&dst[(size_t)rb * DCH + col]) = ob;
    }
}

// ---------------------------------------------------------------------------
// K4: einsum via mma.sync (R8/R9, proven — unchanged).
// ---------------------------------------------------------------------------
#define EM_RS     80
#define EM_A_T    (128 * EM_RS)
#define EM_B_T    (64 * EM_RS)
#define EM_STAGE  (2 * EM_A_T + 2 * EM_B_T)
#define EM_SMEM   (3 * EM_STAGE)

__global__ __launch_bounds__(256, 2) void einsum_mma_kernel()
{
    extern __shared__ char smem[];
    const uint32_t sbase = (uint32_t)__cvta_generic_to_shared(smem);
    const int t    = threadIdx.x;
    const int lane = t & 31;
    const int wid  = t >> 5;
    const int wm   = wid & 3;
    const int wn   = wid >> 2;

    const int bid = blockIdx.x;
    const int d   = bid >> 5;
    const int i0  = ((bid >> 3) & 3) * 128;
    const int k0  = (bid & 7) * 64;

    const __nv_bfloat16* __restrict__ pLh = g_Lh + (size_t)d * NPOS + (size_t)i0 * NRES;
    const __nv_bfloat16* __restrict__ pLl = g_Ll + (size_t)d * NPOS + (size_t)i0 * NRES;
    const __nv_bfloat16* __restrict__ pRh = g_Rh + (size_t)d * NPOS + (size_t)k0 * NRES;
    const __nv_bfloat16* __restrict__ pRl = g_Rl + (size_t)d * NPOS + (size_t)k0 * NRES;

    float acc[2][4][4];
#pragma unroll
    for (int mt = 0; mt < 2; mt++)
#pragma unroll
        for (int nt = 0; nt < 4; nt++)
#pragma unroll
            for (int c = 0; c < 4; c++) acc[mt][nt][c] = 0.0f;

    auto fill = [&](int s) {
        const int buf = s % 3;
        char* base = smem + buf * EM_STAGE;
        const int j0s = s * 32;
        {
            int c0 = t, c1 = t + 256;
            int r0 = c0 >> 2, r1 = c1 >> 2, col0 = c0 & 3, col1 = c1 & 3;
            cp16(base + r0 * EM_RS + col0 * 16,
                 pLh + (size_t)r0 * NRES + j0s + col0 * 8);
            cp16(base + r1 * EM_RS + col1 * 16,
                 pLh + (size_t)r1 * NRES + j0s + col1 * 8);
            cp16(base + EM_A_T + r0 * EM_RS + col0 * 16,
                 pLl + (size_t)r0 * NRES + j0s + col0 * 8);
            cp16(base + EM_A_T + r1 * EM_RS + col1 * 16,
                 pLl + (size_t)r1 * NRES + j0s + col1 * 8);
        }
        {
            int r = t >> 2, col = t & 3;
            cp16(base + 2 * EM_A_T + r * EM_RS + col * 16,
                 pRh + (size_t)r * NRES + j0s + col * 8);
            cp16(base + 2 * EM_A_T + EM_B_T + r * EM_RS + col * 16,
                 pRl + (size_t)r * NRES + j0s + col * 8);
        }
    };

    fill(0); asm volatile("cp.async.commit_group;");
    fill(1); asm volatile("cp.async.commit_group;");

    const uint32_t aOff = (uint32_t)((wm * 32 + ((lane >> 3) & 1) * 8 + (lane & 7)) * EM_RS
                                     + ((lane >> 4) << 4));
    const uint32_t bOff = (uint32_t)((wn * 32 + (lane & 7)) * EM_RS
                                     + (((lane >> 3) & 1) << 4));

    for (int s = 0; s < 16; s++) {
        asm volatile("cp.async.wait_group 1;");
        __syncthreads();
        if (s + 2 < 16) fill(s + 2);
        asm volatile("cp.async.commit_group;");

        const uint32_t sb  = sbase + (s % 3) * EM_STAGE;
        const uint32_t aHb = sb, aLb = sb + EM_A_T;
        const uint32_t bHb = sb + 2 * EM_A_T, bLb = bHb + EM_B_T;

#pragma unroll
        for (int kh = 0; kh < 2; kh++) {
            const uint32_t kb = kh * 32;
            uint32_t aH[2][4], aL[2][4];
            ldsm_x4(aH[0], aHb + aOff + kb);
            ldsm_x4(aH[1], aHb + aOff + 16 * EM_RS + kb);
            ldsm_x4(aL[0], aLb + aOff + kb);
            ldsm_x4(aL[1], aLb + aOff + 16 * EM_RS + kb);
#pragma unroll
            for (int nt = 0; nt < 4; nt++) {
                uint32_t bH[2], bL[2];
                ldsm_x2(bH, bHb + bOff + nt * 8 * EM_RS + kb);
                ldsm_x2(bL, bLb + bOff + nt * 8 * EM_RS + kb);
#pragma unroll
                for (int mt = 0; mt < 2; mt++) {
                    mma16816(acc[mt][nt], aH[mt], bH);
                    mma16816(acc[mt][nt], aH[mt], bL);
                    mma16816(acc[mt][nt], aL[mt], bH);
                }
            }
        }
    }

    float* __restrict__ pOut = g_pret + (size_t)d * NPOS;
    const int g  = lane >> 2;
    const int kc = (lane & 3) * 2;
#pragma unroll
    for (int mt = 0; mt < 2; mt++) {
#pragma unroll
        for (int nt = 0; nt < 4; nt++) {
            const int i = i0 + wm * 32 + mt * 16 + g;
            const int k = k0 + wn * 32 + nt * 8 + kc;
            *reinterpret_cast<float2*>(&pOut[(size_t)i * NRES + k]) =
                make_float2(acc[mt][nt][0], acc[mt][nt][1]);
            *reinterpret_cast<float2*>(&pOut[(size_t)(i + 8) * NRES + k]) =
                make_float2(acc[mt][nt][2], acc[mt][nt][3]);
        }
    }
}

// ---------------------------------------------------------------------------
// T3: pre = pret^T * gate -> split into Ph/Pl bf16 [pos][d] (reuses g_Lh/g_Ll)
// ---------------------------------------------------------------------------
__global__ __launch_bounds__(256) void fuse_gate_kernel()
{
    __shared__ float sP[32][128];
    const int t = threadIdx.x;
    const size_t pos0 = (size_t)blockIdx.x * 32;
    const int d = t >> 1, h = (t & 1) * 16;
#pragma unroll
    for (int q = 0; q < 4; q++) {
        float4 v = reinterpret_cast<const float4*>(g_pret)[
            ((size_t)d * NPOS + pos0 + h) / 4 + q];
        sP[h + q*4 + 0][d] = v.x;
        sP[h + q*4 + 1][d] = v.y;
        sP[h + q*4 + 2][d] = v.z;
        sP[h + q*4 + 3][d] = v.w;
    }
    __syncthreads();
#pragma unroll
    for (int q = 0; q < 4; q++) {
        int idx = t + q * 256;
        int row = idx >> 5, c4 = idx & 31;
        float4 p = *reinterpret_cast<float4*>(&sP[row][c4 * 4]);
        float4 g = reinterpret_cast<const float4*>(g_gate)[(pos0 + row) * 32 + c4];
        p.x *= g.x; p.y *= g.y; p.z *= g.z; p.w *= g.w;
        __nv_bfloat16 h0,l0,h1,l1,h2,l2,h3,l3;
        bsplit(p.x,h0,l0); bsplit(p.y,h1,l1); bsplit(p.z,h2,l2); bsplit(p.w,h3,l3);
        const size_t o = (pos0 + row) * DCH + c4 * 4;
        *reinterpret_cast<uint2*>(&g_Lh[o]) = make_uint2(pack2(h0,h1), pack2(h2,h3));
        *reinterpret_cast<uint2*>(&g_Ll[o]) = make_uint2(pack2(l0,l1), pack2(l2,l3));
    }
}

// ---------------------------------------------------------------------------
extern "C" void kernel_launch(void* const* d_in, const int* in_sizes, int n_in,
                              void* d_out, int out_size)
{
    (void)in_sizes; (void)n_in; (void)out_size;
    const float* pair = (const float*)d_in[0];
    const float* mask = (const float*)d_in[1];
    const float* ln_g = (const float*)d_in[2];
    const float* ln_b = (const float*)d_in[3];
    const float* w_lp = (const float*)d_in[4];
    const float* b_lp = (const float*)d_in[5];
    const float* w_lg = (const float*)d_in[6];
    const float* b_lg = (const float*)d_in[7];
    const float* w_rp = (const float*)d_in[8];
    const float* b_rp = (const float*)d_in[9];
    const float* w_rg = (const float*)d_in[10];
    const float* b_rg = (const float*)d_in[11];
    const float* w_g  = (const float*)d_in[12];
    const float* b_g  = (const float*)d_in[13];
    const float* w_o  = (const float*)d_in[14];
    const float* b_o  = (const float*)d_in[15];
    float* out = (float*)d_out;

    cudaFuncSetAttribute(einsum_mma_kernel,
                         cudaFuncAttributeMaxDynamicSharedMemorySize, EM_SMEM);
    cudaFuncSetAttribute(proj_dual_mma<0,1,0>,
                         cudaFuncAttributeMaxDynamicSharedMemorySize, PJ_SMEM_D);
    cudaFuncSetAttribute(proj_dual_mma<2,3,1>,
                         cudaFuncAttributeMaxDynamicSharedMemorySize, PJ_SMEM_D);
    cudaFuncSetAttribute(proj_single_mma<4,1>,
                         cudaFuncAttributeMaxDynamicSharedMemorySize, PJ_SMEM_S);
    cudaFuncSetAttribute(proj_single_mma<5,0>,
                         cudaFuncAttributeMaxDynamicSharedMemorySize, PJ_SMEM_S);

    prep_weights<<<6, 256>>>(w_lp, w_lg, w_rp, w_rg, w_g, w_o);
    ln_split_kernel<<<NPOS / 8, 256>>>(pair, ln_g, ln_b);
    proj_dual_mma<0,1,0><<<NPOS / 64, 256, PJ_SMEM_D>>>(b_lp, b_lg, mask);
    proj_dual_mma<2,3,1><<<NPOS / 64, 256, PJ_SMEM_D>>>(b_rp, b_rg, mask);
    proj_single_mma<4,1><<<NPOS / 64, 256, PJ_SMEM_S>>>(b_g, nullptr);
    einsum_mma_kernel<<<4096, 256, EM_SMEM>>>();
    fuse_gate_kernel<<<NPOS / 32, 256>>>();
    proj_single_mma<5,0><<<NPOS / 64, 256, PJ_SMEM_S>>>(b_o, out);
}